// round 3
// baseline (speedup 1.0000x reference)
#include <cuda_runtime.h>
#include <math.h>
#include <stdint.h>

// Problem dims
#define Bsz  4
#define Nseq 2048
#define Dmod 512
#define Hh   8
#define DHd  64
#define FFd  1024
#define Mrows (Bsz*Nseq)   // 8192

// ---------------- scratch (static device allocations) ----------------
__device__ float g_qk0[Mrows*Dmod];
__device__ float g_qk1[Mrows*Dmod];
__device__ float g_v0 [Mrows*Dmod];
__device__ float g_v1 [Mrows*Dmod];
__device__ float g_a0 [Mrows*Dmod];
__device__ float g_a1 [Mrows*Dmod];
__device__ float g_hcat[Mrows*FFd];
__device__ float g_hmid[Mrows*FFd];

// ---------------- tf32 helpers ----------------
__device__ __forceinline__ float f2tf(float x) {
    uint32_t u;
    asm("cvt.rna.tf32.f32 %0, %1;" : "=r"(u) : "f"(x));
    return __uint_as_float(u);
}

__device__ __forceinline__ void mma_tf32(float d[4], const uint32_t a[4], const uint32_t b[2]) {
    asm volatile(
        "mma.sync.aligned.m16n8k8.row.col.f32.tf32.tf32.f32 "
        "{%0,%1,%2,%3}, {%4,%5,%6,%7}, {%8,%9}, {%0,%1,%2,%3};\n"
        : "+f"(d[0]), "+f"(d[1]), "+f"(d[2]), "+f"(d[3])
        : "r"(a[0]), "r"(a[1]), "r"(a[2]), "r"(a[3]), "r"(b[0]), "r"(b[1]));
}

// ---------------- TF32 GEMM: C[M,N] = A[M,K] * W[N,K]^T + bias (+res) ----------------
// 128x128 block tile, BK=32, 8 warps (2x4), each warp 64x32 (4x4 m16n8k8 atoms).
#define BM 128
#define BN 128
#define BK 32

__global__ __launch_bounds__(256) void gemm_tf32(
    const float* __restrict__ A, const float* __restrict__ W,
    const float* __restrict__ bias, const float* __restrict__ res,
    float* __restrict__ C, int M, int N, int K)
{
    __shared__ float As[BM][BK + 4];
    __shared__ float Bs[BN][BK + 4];

    const int tid  = threadIdx.x;
    const int wid  = tid >> 5, lane = tid & 31;
    const int g    = lane >> 2, tig = lane & 3;
    const int wm   = wid & 1,  wn  = wid >> 1;   // 2 x 4 warp grid

    const int lr = tid >> 3;         // 0..31 load row base
    const int lc = (tid & 7) * 4;    // 0..28 load col (float4)

    const float* Ag = A + (size_t)(blockIdx.y * BM + lr) * K + lc;
    const float* Wg = W + (size_t)(blockIdx.x * BN + lr) * K + lc;

    float acc[4][4][4];
    #pragma unroll
    for (int m = 0; m < 4; m++)
        #pragma unroll
        for (int n = 0; n < 4; n++)
            #pragma unroll
            for (int j = 0; j < 4; j++) acc[m][n][j] = 0.f;

    float4 ar[4], br[4];
    #pragma unroll
    for (int i = 0; i < 4; i++) {
        ar[i] = *(const float4*)(Ag + (size_t)i * 32 * K);
        br[i] = *(const float4*)(Wg + (size_t)i * 32 * K);
    }

    const int T = K / BK;
    for (int t = 0; t < T; t++) {
        __syncthreads();
        #pragma unroll
        for (int i = 0; i < 4; i++) {
            As[lr + 32*i][lc+0] = f2tf(ar[i].x); As[lr + 32*i][lc+1] = f2tf(ar[i].y);
            As[lr + 32*i][lc+2] = f2tf(ar[i].z); As[lr + 32*i][lc+3] = f2tf(ar[i].w);
            Bs[lr + 32*i][lc+0] = f2tf(br[i].x); Bs[lr + 32*i][lc+1] = f2tf(br[i].y);
            Bs[lr + 32*i][lc+2] = f2tf(br[i].z); Bs[lr + 32*i][lc+3] = f2tf(br[i].w);
        }
        __syncthreads();
        if (t + 1 < T) {
            #pragma unroll
            for (int i = 0; i < 4; i++) {
                ar[i] = *(const float4*)(Ag + (t+1)*BK + (size_t)i * 32 * K);
                br[i] = *(const float4*)(Wg + (t+1)*BK + (size_t)i * 32 * K);
            }
        }
        #pragma unroll
        for (int kq = 0; kq < 4; kq++) {
            uint32_t af[4][4], bf[4][2];
            #pragma unroll
            for (int m = 0; m < 4; m++) {
                int r = wm*64 + m*16 + g;
                af[m][0] = __float_as_uint(As[r    ][kq*8 + tig]);
                af[m][1] = __float_as_uint(As[r + 8][kq*8 + tig]);
                af[m][2] = __float_as_uint(As[r    ][kq*8 + tig + 4]);
                af[m][3] = __float_as_uint(As[r + 8][kq*8 + tig + 4]);
            }
            #pragma unroll
            for (int n = 0; n < 4; n++) {
                int r = wn*32 + n*8 + g;
                bf[n][0] = __float_as_uint(Bs[r][kq*8 + tig]);
                bf[n][1] = __float_as_uint(Bs[r][kq*8 + tig + 4]);
            }
            #pragma unroll
            for (int m = 0; m < 4; m++)
                #pragma unroll
                for (int n = 0; n < 4; n++)
                    mma_tf32(acc[m][n], af[m], bf[n]);
        }
    }

    const int rb = blockIdx.y * BM + wm * 64;
    const int cb = blockIdx.x * BN + wn * 32;
    #pragma unroll
    for (int m = 0; m < 4; m++) {
        #pragma unroll
        for (int n = 0; n < 4; n++) {
            int row0 = rb + m*16 + g;
            int col  = cb + n*8 + tig*2;
            float b0 = bias[col], b1 = bias[col+1];
            float v0 = acc[m][n][0] + b0, v1 = acc[m][n][1] + b1;
            float v2 = acc[m][n][2] + b0, v3 = acc[m][n][3] + b1;
            if (res) {
                const float* r0p = res + (size_t)row0 * N + col;
                const float* r1p = res + (size_t)(row0+8) * N + col;
                v0 += r0p[0]; v1 += r0p[1];
                v2 += r1p[0]; v3 += r1p[1];
            }
            *(float2*)(C + (size_t)row0     * N + col) = make_float2(v0, v1);
            *(float2*)(C + (size_t)(row0+8) * N + col) = make_float2(v2, v3);
        }
    }
}

// ---------------- Tensor-core flash attention (tf32) ----------------
// Block: 256 threads, 8 warps; 128 q-rows per block (warp owns 16 rows x full width).
// Key tiles of 64. S via mma -> warp-local online softmax -> P through smem -> PV mma.
#define KT 64
#define ATTN_SMEM ((2*KT*68 + 128*68) * 4)   // Ks + Vs + Ps = 69632 bytes

__global__ __launch_bounds__(256) void attn_tc(
    const float* __restrict__ Q, const float* __restrict__ Kt,
    const float* __restrict__ V, float* __restrict__ O)
{
    extern __shared__ float smbuf[];
    float (*Ks)[68] = (float(*)[68])smbuf;                 // KT x 68
    float (*Vs)[68] = (float(*)[68])(smbuf + KT*68);       // KT x 68
    float (*Ps)[68] = (float(*)[68])(smbuf + 2*KT*68);     // 128 x 68

    const int tid  = threadIdx.x;
    const int wid  = tid >> 5, lane = tid & 31;
    const int g    = lane >> 2, tig = lane & 3;

    const int bh = blockIdx.x;
    const int b  = bh >> 3, h = bh & 7;
    const size_t base = (size_t)b * (Nseq * Dmod) + (size_t)h * DHd;
    const int qrow = blockIdx.y * 128 + wid * 16;

    // Q fragments (warp's 16 rows x 64 cols), kept in registers for all key tiles
    uint32_t qf[8][4];
    {
        const float* qp = Q + base + (size_t)(qrow + g) * Dmod;
        #pragma unroll
        for (int ks = 0; ks < 8; ks++) {
            qf[ks][0] = __float_as_uint(f2tf(qp[ks*8 + tig]));
            qf[ks][1] = __float_as_uint(f2tf(qp[8*Dmod + ks*8 + tig]));
            qf[ks][2] = __float_as_uint(f2tf(qp[ks*8 + tig + 4]));
            qf[ks][3] = __float_as_uint(f2tf(qp[8*Dmod + ks*8 + tig + 4]));
        }
    }

    float oacc[8][4];
    #pragma unroll
    for (int n = 0; n < 8; n++)
        #pragma unroll
        for (int j = 0; j < 4; j++) oacc[n][j] = 0.f;
    float m0 = -1e30f, m1 = -1e30f, l0 = 0.f, l1 = 0.f;

    const int lr = tid >> 2;          // 0..63
    const int lc = (tid & 3) * 4;     // 0,4,8,12 (+16*i)
    const float* Kg = Kt + base + (size_t)lr * Dmod + lc;
    const float* Vg = V  + base + (size_t)lr * Dmod + lc;

    const int pr = wid * 16 + g;

    for (int kt = 0; kt < Nseq / KT; kt++) {
        __syncthreads();
        size_t off = (size_t)kt * KT * Dmod;
        #pragma unroll
        for (int i = 0; i < 4; i++) {
            float4 kv = *(const float4*)(Kg + off + i*16);
            float4 vv = *(const float4*)(Vg + off + i*16);
            Ks[lr][lc + 16*i + 0] = f2tf(kv.x); Ks[lr][lc + 16*i + 1] = f2tf(kv.y);
            Ks[lr][lc + 16*i + 2] = f2tf(kv.z); Ks[lr][lc + 16*i + 3] = f2tf(kv.w);
            Vs[lr][lc + 16*i + 0] = f2tf(vv.x); Vs[lr][lc + 16*i + 1] = f2tf(vv.y);
            Vs[lr][lc + 16*i + 2] = f2tf(vv.z); Vs[lr][lc + 16*i + 3] = f2tf(vv.w);
        }
        __syncthreads();

        // S = Q K^T  (warp: 16 rows x 64 keys)
        float sacc[8][4];
        #pragma unroll
        for (int n = 0; n < 8; n++)
            #pragma unroll
            for (int j = 0; j < 4; j++) sacc[n][j] = 0.f;

        #pragma unroll
        for (int ks = 0; ks < 8; ks++) {
            uint32_t bf[8][2];
            #pragma unroll
            for (int n = 0; n < 8; n++) {
                bf[n][0] = __float_as_uint(Ks[n*8 + g][ks*8 + tig]);
                bf[n][1] = __float_as_uint(Ks[n*8 + g][ks*8 + tig + 4]);
            }
            #pragma unroll
            for (int n = 0; n < 8; n++) mma_tf32(sacc[n], qf[ks], bf[n]);
        }

        // online softmax (rows g and g+8 of warp tile)
        float t0 = -1e30f, t1 = -1e30f;
        #pragma unroll
        for (int n = 0; n < 8; n++) {
            sacc[n][0] *= 0.125f; sacc[n][1] *= 0.125f;
            sacc[n][2] *= 0.125f; sacc[n][3] *= 0.125f;
            t0 = fmaxf(t0, fmaxf(sacc[n][0], sacc[n][1]));
            t1 = fmaxf(t1, fmaxf(sacc[n][2], sacc[n][3]));
        }
        t0 = fmaxf(t0, __shfl_xor_sync(0xffffffffu, t0, 1));
        t0 = fmaxf(t0, __shfl_xor_sync(0xffffffffu, t0, 2));
        t1 = fmaxf(t1, __shfl_xor_sync(0xffffffffu, t1, 1));
        t1 = fmaxf(t1, __shfl_xor_sync(0xffffffffu, t1, 2));

        float mn0 = fmaxf(m0, t0), mn1 = fmaxf(m1, t1);
        float c0 = __expf(m0 - mn0), c1 = __expf(m1 - mn1);
        m0 = mn0; m1 = mn1;

        float ps0 = 0.f, ps1 = 0.f;
        #pragma unroll
        for (int n = 0; n < 8; n++) {
            float p00 = __expf(sacc[n][0] - m0), p01 = __expf(sacc[n][1] - m0);
            float p10 = __expf(sacc[n][2] - m1), p11 = __expf(sacc[n][3] - m1);
            ps0 += p00 + p01; ps1 += p10 + p11;
            sacc[n][0] = p00; sacc[n][1] = p01; sacc[n][2] = p10; sacc[n][3] = p11;
        }
        ps0 += __shfl_xor_sync(0xffffffffu, ps0, 1);
        ps0 += __shfl_xor_sync(0xffffffffu, ps0, 2);
        ps1 += __shfl_xor_sync(0xffffffffu, ps1, 1);
        ps1 += __shfl_xor_sync(0xffffffffu, ps1, 2);
        l0 = l0 * c0 + ps0;
        l1 = l1 * c1 + ps1;
        #pragma unroll
        for (int n = 0; n < 8; n++) {
            oacc[n][0] *= c0; oacc[n][1] *= c0;
            oacc[n][2] *= c1; oacc[n][3] *= c1;
        }

        // write P tile to smem (A-operand for PV)
        #pragma unroll
        for (int n = 0; n < 8; n++) {
            Ps[pr    ][n*8 + tig*2    ] = f2tf(sacc[n][0]);
            Ps[pr    ][n*8 + tig*2 + 1] = f2tf(sacc[n][1]);
            Ps[pr + 8][n*8 + tig*2    ] = f2tf(sacc[n][2]);
            Ps[pr + 8][n*8 + tig*2 + 1] = f2tf(sacc[n][3]);
        }
        __syncthreads();

        // O += P V
        #pragma unroll
        for (int ks = 0; ks < 8; ks++) {
            uint32_t af[4];
            af[0] = __float_as_uint(Ps[pr    ][ks*8 + tig]);
            af[1] = __float_as_uint(Ps[pr + 8][ks*8 + tig]);
            af[2] = __float_as_uint(Ps[pr    ][ks*8 + tig + 4]);
            af[3] = __float_as_uint(Ps[pr + 8][ks*8 + tig + 4]);
            #pragma unroll
            for (int n = 0; n < 8; n++) {
                uint32_t bf[2];
                bf[0] = __float_as_uint(Vs[ks*8 + tig    ][n*8 + g]);
                bf[1] = __float_as_uint(Vs[ks*8 + tig + 4][n*8 + g]);
                mma_tf32(oacc[n], af, bf);
            }
        }
    }

    float i0 = 1.f / l0, i1 = 1.f / l1;
    float* Op = O + base + (size_t)(qrow + g) * Dmod;
    #pragma unroll
    for (int n = 0; n < 8; n++) {
        *(float2*)(Op + n*8 + tig*2)            = make_float2(oacc[n][0]*i0, oacc[n][1]*i0);
        *(float2*)(Op + 8*Dmod + n*8 + tig*2)   = make_float2(oacc[n][2]*i1, oacc[n][3]*i1);
    }
}

// ---------------- concat [x | m] -> hcat [M, 1024] ----------------
__global__ void concat_kernel(const float* __restrict__ X, const float* __restrict__ Mm,
                              float* __restrict__ Out)
{
    int idx = blockIdx.x * blockDim.x + threadIdx.x;
    if (idx >= Mrows * FFd) return;
    int m = idx >> 10;
    int c = idx & 1023;
    Out[idx] = (c < Dmod) ? X[(size_t)m * Dmod + c] : Mm[(size_t)m * Dmod + (c - Dmod)];
}

// ---------------- LayerNorm(1024) + exact GELU, in place ----------------
__global__ __launch_bounds__(256) void ln_gelu_kernel(
    float* __restrict__ Hm, const float* __restrict__ gw, const float* __restrict__ bw)
{
    __shared__ float red1[8];
    __shared__ float red2[8];
    __shared__ float s_mu, s_inv;

    const int row = blockIdx.x;
    const int tid = threadIdx.x;
    float* hp = Hm + (size_t)row * FFd;

    float v[4];
    float s = 0.f;
    #pragma unroll
    for (int i = 0; i < 4; i++) { v[i] = hp[tid + i*256]; s += v[i]; }

    #pragma unroll
    for (int off = 16; off; off >>= 1) s += __shfl_xor_sync(0xffffffffu, s, off);
    if ((tid & 31) == 0) red1[tid >> 5] = s;
    __syncthreads();
    if (tid == 0) {
        float t = 0.f;
        #pragma unroll
        for (int w = 0; w < 8; w++) t += red1[w];
        s_mu = t * (1.f / FFd);
    }
    __syncthreads();
    const float mu = s_mu;

    float ss = 0.f;
    #pragma unroll
    for (int i = 0; i < 4; i++) { float d = v[i] - mu; ss += d*d; }
    #pragma unroll
    for (int off = 16; off; off >>= 1) ss += __shfl_xor_sync(0xffffffffu, ss, off);
    if ((tid & 31) == 0) red2[tid >> 5] = ss;
    __syncthreads();
    if (tid == 0) {
        float t = 0.f;
        #pragma unroll
        for (int w = 0; w < 8; w++) t += red2[w];
        s_inv = rsqrtf(t * (1.f / FFd) + 1e-5f);
    }
    __syncthreads();
    const float inv = s_inv;

    #pragma unroll
    for (int i = 0; i < 4; i++) {
        int c = tid + i*256;
        float x = (v[i] - mu) * inv * gw[c] + bw[c];
        hp[c] = 0.5f * x * (1.f + erff(x * 0.70710678118654752f));
    }
}

// ---------------- launcher ----------------
extern "C" void kernel_launch(void* const* d_in, const int* in_sizes, int n_in,
                              void* d_out, int out_size)
{
    const float* x0  = (const float*)d_in[0];
    const float* x1  = (const float*)d_in[1];
    const float* Wqk = (const float*)d_in[2];
    const float* bqk = (const float*)d_in[3];
    const float* Wv  = (const float*)d_in[4];
    const float* bv  = (const float*)d_in[5];
    const float* Wo  = (const float*)d_in[6];
    const float* bo  = (const float*)d_in[7];
    const float* Wf1 = (const float*)d_in[8];
    const float* bf1 = (const float*)d_in[9];
    const float* lng = (const float*)d_in[10];
    const float* lnb = (const float*)d_in[11];
    const float* Wf2 = (const float*)d_in[12];
    const float* bf2 = (const float*)d_in[13];
    float* out = (float*)d_out;

    float *qk0, *qk1, *v0, *v1, *a0, *a1, *hcat, *hmid;
    cudaGetSymbolAddress((void**)&qk0,  g_qk0);
    cudaGetSymbolAddress((void**)&qk1,  g_qk1);
    cudaGetSymbolAddress((void**)&v0,   g_v0);
    cudaGetSymbolAddress((void**)&v1,   g_v1);
    cudaGetSymbolAddress((void**)&a0,   g_a0);
    cudaGetSymbolAddress((void**)&a1,   g_a1);
    cudaGetSymbolAddress((void**)&hcat, g_hcat);
    cudaGetSymbolAddress((void**)&hmid, g_hmid);

    cudaFuncSetAttribute(attn_tc, cudaFuncAttributeMaxDynamicSharedMemorySize, ATTN_SMEM);

    dim3 g512(Dmod/128, Mrows/128);   // (4, 64)
    dim3 g1024(FFd/128, Mrows/128);   // (8, 64)
    dim3 ga(Bsz*Hh, Nseq/128);        // (32, 16)
    int ctotal = Mrows * FFd;
    int cblocks = (ctotal + 255) / 256;

    // projections
    gemm_tf32<<<g512, 256>>>(x0, Wqk, bqk, nullptr, qk0, Mrows, Dmod, Dmod);
    gemm_tf32<<<g512, 256>>>(x1, Wqk, bqk, nullptr, qk1, Mrows, Dmod, Dmod);
    gemm_tf32<<<g512, 256>>>(x0, Wv,  bv,  nullptr, v0,  Mrows, Dmod, Dmod);
    gemm_tf32<<<g512, 256>>>(x1, Wv,  bv,  nullptr, v1,  Mrows, Dmod, Dmod);

    // cross attention
    attn_tc<<<ga, 256, ATTN_SMEM>>>(qk0, qk1, v1, a0);
    attn_tc<<<ga, 256, ATTN_SMEM>>>(qk1, qk0, v0, a1);

    // output projection (reuse v1/v0 as m0/m1)
    gemm_tf32<<<g512, 256>>>(a0, Wo, bo, nullptr, v1, Mrows, Dmod, Dmod);
    gemm_tf32<<<g512, 256>>>(a1, Wo, bo, nullptr, v0, Mrows, Dmod, Dmod);

    // FFN stream 0
    concat_kernel<<<cblocks, 256>>>(x0, v1, hcat);
    gemm_tf32<<<g1024, 256>>>(hcat, Wf1, bf1, nullptr, hmid, Mrows, FFd, FFd);
    ln_gelu_kernel<<<Mrows, 256>>>(hmid, lng, lnb);
    gemm_tf32<<<g512, 256>>>(hmid, Wf2, bf2, x0, out, Mrows, Dmod, FFd);

    // FFN stream 1
    concat_kernel<<<cblocks, 256>>>(x1, v0, hcat);
    gemm_tf32<<<g1024, 256>>>(hcat, Wf1, bf1, nullptr, hmid, Mrows, FFd, FFd);
    ln_gelu_kernel<<<Mrows, 256>>>(hmid, lng, lnb);
    gemm_tf32<<<g512, 256>>>(hmid, Wf2, bf2, x1, out + (size_t)Mrows*Dmod, Mrows, Dmod, FFd);
}

// round 5
// speedup vs baseline: 1.4877x; 1.4877x over previous
#include <cuda_runtime.h>
#include <math.h>
#include <stdint.h>

#define Bsz  4
#define Nseq 2048
#define Dmod 512
#define Hh   8
#define DHd  64
#define FFd  1024
#define Mrows (Bsz*Nseq)   // 8192

// ---------------- scratch ----------------
__device__ float g_qk0[Mrows*Dmod];
__device__ float g_qk1[Mrows*Dmod];
__device__ float g_v0 [Mrows*Dmod];
__device__ float g_v1 [Mrows*Dmod];
__device__ float g_a0 [Mrows*Dmod];
__device__ float g_a1 [Mrows*Dmod];
__device__ float g_hmid[Mrows*FFd];

// ---------------- helpers ----------------
__device__ __forceinline__ float f2tf(float x) {
    uint32_t u;
    asm("cvt.rna.tf32.f32 %0, %1;" : "=r"(u) : "f"(x));
    return __uint_as_float(u);
}
__device__ __forceinline__ void mma_tf32(float d[4], const uint32_t a[4], const uint32_t b[2]) {
    asm volatile(
        "mma.sync.aligned.m16n8k8.row.col.f32.tf32.tf32.f32 "
        "{%0,%1,%2,%3}, {%4,%5,%6,%7}, {%8,%9}, {%0,%1,%2,%3};\n"
        : "+f"(d[0]), "+f"(d[1]), "+f"(d[2]), "+f"(d[3])
        : "r"(a[0]), "r"(a[1]), "r"(a[2]), "r"(a[3]), "r"(b[0]), "r"(b[1]));
}
__device__ __forceinline__ void ldsm4(uint32_t r[4], uint32_t addr) {
    asm volatile("ldmatrix.sync.aligned.m8n8.x4.shared.b16 {%0,%1,%2,%3}, [%4];"
        : "=r"(r[0]), "=r"(r[1]), "=r"(r[2]), "=r"(r[3]) : "r"(addr));
}
// float offset within a [rows][8 units of 16B] panel, XOR-swizzled (pitch 32 floats)
__device__ __forceinline__ int swz8(int row, int u) {
    return row * 32 + ((u ^ (row & 7)) << 2);
}

// ---------------- TF32 GEMM, ldmatrix + double buffer ----------------
// C[M,N] = A[M,K]*W[N,K]^T + bias (+res). 128x128 tile, BK=32, 8 warps (2x4).
// CAT: A is virtual concat [A | A2], each M x 512 (requires K=1024).
// smem floats: A stages @0,4096 ; B stages @8192,12288  (64 KB dynamic)
template<bool CAT>
__global__ __launch_bounds__(256, 2) void gemm_tc(
    const float* __restrict__ A, const float* __restrict__ A2,
    const float* __restrict__ W,
    const float* __restrict__ bias, const float* __restrict__ res,
    float* __restrict__ C, int M, int N, int K)
{
    extern __shared__ float sm[];
    const uint32_t smB = (uint32_t)__cvta_generic_to_shared(sm);

    const int tid  = threadIdx.x;
    const int wid  = tid >> 5, lane = tid & 31;
    const int g    = lane >> 2, tig = lane & 3;
    const int wm   = wid & 1,  wn   = wid >> 1;
    const int lr   = tid >> 3;       // 0..31
    const int lu   = tid & 7;        // unit
    const int j    = lane >> 3;      // ldmatrix matrix id
    const int jr   = (j & 1) * 8, jc = (j >> 1);
    const int l7   = lane & 7;

    const int arow0 = blockIdx.y * 128;
    const int brow0 = blockIdx.x * 128;

    float acc[4][4][4];
    #pragma unroll
    for (int m = 0; m < 4; m++)
        #pragma unroll
        for (int n = 0; n < 4; n++)
            #pragma unroll
            for (int q = 0; q < 4; q++) acc[m][n][q] = 0.f;

    const int T = K / 32;
    float4 ar[4], br[4];

    auto loadA = [&](int i, int colg) -> float4 {
        int row = arow0 + lr + 32*i;
        if (CAT) {
            return (colg < 512) ? *(const float4*)(A  + (size_t)row*512 + colg)
                                : *(const float4*)(A2 + (size_t)row*512 + colg - 512);
        }
        return *(const float4*)(A + (size_t)row*K + colg);
    };

    // prologue: tile 0
    #pragma unroll
    for (int i = 0; i < 4; i++) {
        ar[i] = loadA(i, lu*4);
        br[i] = *(const float4*)(W + (size_t)(brow0 + lr + 32*i)*K + lu*4);
    }
    #pragma unroll
    for (int i = 0; i < 4; i++) {
        int off = swz8(lr + 32*i, lu);
        *(float4*)(sm + off)        = make_float4(f2tf(ar[i].x), f2tf(ar[i].y), f2tf(ar[i].z), f2tf(ar[i].w));
        *(float4*)(sm + 8192 + off) = make_float4(f2tf(br[i].x), f2tf(br[i].y), f2tf(br[i].z), f2tf(br[i].w));
    }
    __syncthreads();

    for (int t = 0; t < T; t++) {
        if (t + 1 < T) {
            int colg = (t+1)*32 + lu*4;
            #pragma unroll
            for (int i = 0; i < 4; i++) {
                ar[i] = loadA(i, colg);
                br[i] = *(const float4*)(W + (size_t)(brow0 + lr + 32*i)*K + colg);
            }
        }

        const uint32_t aB = smB + ((t & 1) * 4096) * 4;
        const uint32_t bB = aB + 8192 * 4;

        #pragma unroll
        for (int kq = 0; kq < 4; kq++) {
            const int u = kq*2 + jc;
            uint32_t af[4][4], bf[4][2];
            #pragma unroll
            for (int m = 0; m < 4; m++)
                ldsm4(af[m], aB + swz8(wm*64 + m*16 + jr + l7, u) * 4);
            #pragma unroll
            for (int np = 0; np < 2; np++) {
                uint32_t t4[4];
                ldsm4(t4, bB + swz8(wn*32 + np*16 + jr + l7, u) * 4);
                bf[2*np  ][0] = t4[0]; bf[2*np  ][1] = t4[2];
                bf[2*np+1][0] = t4[1]; bf[2*np+1][1] = t4[3];
            }
            #pragma unroll
            for (int m = 0; m < 4; m++)
                #pragma unroll
                for (int n = 0; n < 4; n++)
                    mma_tf32(acc[m][n], af[m], bf[n]);
        }

        if (t + 1 < T) {
            int st = ((t+1) & 1) * 4096;
            #pragma unroll
            for (int i = 0; i < 4; i++) {
                int off = st + swz8(lr + 32*i, lu);
                *(float4*)(sm + off)        = make_float4(f2tf(ar[i].x), f2tf(ar[i].y), f2tf(ar[i].z), f2tf(ar[i].w));
                *(float4*)(sm + 8192 + off) = make_float4(f2tf(br[i].x), f2tf(br[i].y), f2tf(br[i].z), f2tf(br[i].w));
            }
        }
        __syncthreads();
    }

    const int rb = arow0 + wm * 64;
    const int cb = brow0 + wn * 32;
    #pragma unroll
    for (int m = 0; m < 4; m++) {
        #pragma unroll
        for (int n = 0; n < 4; n++) {
            int row0 = rb + m*16 + g;
            int col  = cb + n*8 + tig*2;
            float b0 = bias[col], b1 = bias[col+1];
            float v0 = acc[m][n][0] + b0, v1 = acc[m][n][1] + b1;
            float v2 = acc[m][n][2] + b0, v3 = acc[m][n][3] + b1;
            if (res) {
                const float* r0p = res + (size_t)row0 * N + col;
                const float* r1p = res + (size_t)(row0+8) * N + col;
                v0 += r0p[0]; v1 += r0p[1];
                v2 += r1p[0]; v3 += r1p[1];
            }
            *(float2*)(C + (size_t)row0     * N + col) = make_float2(v0, v1);
            *(float2*)(C + (size_t)(row0+8) * N + col) = make_float2(v2, v3);
        }
    }
}

// ---------------- Tensor-core flash attention (proven in R2) ----------------
#define KT 64
#define ATTN_SMEM ((2*KT*68 + 128*68) * 4)

__global__ __launch_bounds__(256) void attn_tc(
    const float* __restrict__ Q, const float* __restrict__ Kt,
    const float* __restrict__ V, float* __restrict__ O)
{
    extern __shared__ float smbuf[];
    float (*Ks)[68] = (float(*)[68])smbuf;
    float (*Vs)[68] = (float(*)[68])(smbuf + KT*68);
    float (*Ps)[68] = (float(*)[68])(smbuf + 2*KT*68);

    const int tid  = threadIdx.x;
    const int wid  = tid >> 5, lane = tid & 31;
    const int g    = lane >> 2, tig = lane & 3;

    const int bh = blockIdx.x;
    const int b  = bh >> 3, h = bh & 7;
    const size_t base = (size_t)b * (Nseq * Dmod) + (size_t)h * DHd;
    const int qrow = blockIdx.y * 128 + wid * 16;

    uint32_t qf[8][4];
    {
        const float* qp = Q + base + (size_t)(qrow + g) * Dmod;
        #pragma unroll
        for (int ks = 0; ks < 8; ks++) {
            qf[ks][0] = __float_as_uint(f2tf(qp[ks*8 + tig]));
            qf[ks][1] = __float_as_uint(f2tf(qp[8*Dmod + ks*8 + tig]));
            qf[ks][2] = __float_as_uint(f2tf(qp[ks*8 + tig + 4]));
            qf[ks][3] = __float_as_uint(f2tf(qp[8*Dmod + ks*8 + tig + 4]));
        }
    }

    float oacc[8][4];
    #pragma unroll
    for (int n = 0; n < 8; n++)
        #pragma unroll
        for (int q = 0; q < 4; q++) oacc[n][q] = 0.f;
    float m0 = -1e30f, m1 = -1e30f, l0 = 0.f, l1 = 0.f;

    const int lr = tid >> 2;
    const int lc = (tid & 3) * 4;
    const float* Kg = Kt + base + (size_t)lr * Dmod + lc;
    const float* Vg = V  + base + (size_t)lr * Dmod + lc;
    const int pr = wid * 16 + g;

    for (int kt = 0; kt < Nseq / KT; kt++) {
        __syncthreads();
        size_t off = (size_t)kt * KT * Dmod;
        #pragma unroll
        for (int i = 0; i < 4; i++) {
            float4 kv = *(const float4*)(Kg + off + i*16);
            float4 vv = *(const float4*)(Vg + off + i*16);
            Ks[lr][lc + 16*i + 0] = f2tf(kv.x); Ks[lr][lc + 16*i + 1] = f2tf(kv.y);
            Ks[lr][lc + 16*i + 2] = f2tf(kv.z); Ks[lr][lc + 16*i + 3] = f2tf(kv.w);
            Vs[lr][lc + 16*i + 0] = f2tf(vv.x); Vs[lr][lc + 16*i + 1] = f2tf(vv.y);
            Vs[lr][lc + 16*i + 2] = f2tf(vv.z); Vs[lr][lc + 16*i + 3] = f2tf(vv.w);
        }
        __syncthreads();

        float sacc[8][4];
        #pragma unroll
        for (int n = 0; n < 8; n++)
            #pragma unroll
            for (int q = 0; q < 4; q++) sacc[n][q] = 0.f;

        #pragma unroll
        for (int ks = 0; ks < 8; ks++) {
            uint32_t bf[8][2];
            #pragma unroll
            for (int n = 0; n < 8; n++) {
                bf[n][0] = __float_as_uint(Ks[n*8 + g][ks*8 + tig]);
                bf[n][1] = __float_as_uint(Ks[n*8 + g][ks*8 + tig + 4]);
            }
            #pragma unroll
            for (int n = 0; n < 8; n++) mma_tf32(sacc[n], qf[ks], bf[n]);
        }

        float t0 = -1e30f, t1 = -1e30f;
        #pragma unroll
        for (int n = 0; n < 8; n++) {
            sacc[n][0] *= 0.125f; sacc[n][1] *= 0.125f;
            sacc[n][2] *= 0.125f; sacc[n][3] *= 0.125f;
            t0 = fmaxf(t0, fmaxf(sacc[n][0], sacc[n][1]));
            t1 = fmaxf(t1, fmaxf(sacc[n][2], sacc[n][3]));
        }
        t0 = fmaxf(t0, __shfl_xor_sync(0xffffffffu, t0, 1));
        t0 = fmaxf(t0, __shfl_xor_sync(0xffffffffu, t0, 2));
        t1 = fmaxf(t1, __shfl_xor_sync(0xffffffffu, t1, 1));
        t1 = fmaxf(t1, __shfl_xor_sync(0xffffffffu, t1, 2));

        float mn0 = fmaxf(m0, t0), mn1 = fmaxf(m1, t1);
        float c0 = __expf(m0 - mn0), c1 = __expf(m1 - mn1);
        m0 = mn0; m1 = mn1;

        float ps0 = 0.f, ps1 = 0.f;
        #pragma unroll
        for (int n = 0; n < 8; n++) {
            float p00 = __expf(sacc[n][0] - m0), p01 = __expf(sacc[n][1] - m0);
            float p10 = __expf(sacc[n][2] - m1), p11 = __expf(sacc[n][3] - m1);
            ps0 += p00 + p01; ps1 += p10 + p11;
            sacc[n][0] = p00; sacc[n][1] = p01; sacc[n][2] = p10; sacc[n][3] = p11;
        }
        ps0 += __shfl_xor_sync(0xffffffffu, ps0, 1);
        ps0 += __shfl_xor_sync(0xffffffffu, ps0, 2);
        ps1 += __shfl_xor_sync(0xffffffffu, ps1, 1);
        ps1 += __shfl_xor_sync(0xffffffffu, ps1, 2);
        l0 = l0 * c0 + ps0;
        l1 = l1 * c1 + ps1;
        #pragma unroll
        for (int n = 0; n < 8; n++) {
            oacc[n][0] *= c0; oacc[n][1] *= c0;
            oacc[n][2] *= c1; oacc[n][3] *= c1;
        }

        #pragma unroll
        for (int n = 0; n < 8; n++) {
            Ps[pr    ][n*8 + tig*2    ] = f2tf(sacc[n][0]);
            Ps[pr    ][n*8 + tig*2 + 1] = f2tf(sacc[n][1]);
            Ps[pr + 8][n*8 + tig*2    ] = f2tf(sacc[n][2]);
            Ps[pr + 8][n*8 + tig*2 + 1] = f2tf(sacc[n][3]);
        }
        __syncthreads();

        #pragma unroll
        for (int ks = 0; ks < 8; ks++) {
            uint32_t af[4];
            af[0] = __float_as_uint(Ps[pr    ][ks*8 + tig]);
            af[1] = __float_as_uint(Ps[pr + 8][ks*8 + tig]);
            af[2] = __float_as_uint(Ps[pr    ][ks*8 + tig + 4]);
            af[3] = __float_as_uint(Ps[pr + 8][ks*8 + tig + 4]);
            #pragma unroll
            for (int n = 0; n < 8; n++) {
                uint32_t bf[2];
                bf[0] = __float_as_uint(Vs[ks*8 + tig    ][n*8 + g]);
                bf[1] = __float_as_uint(Vs[ks*8 + tig + 4][n*8 + g]);
                mma_tf32(oacc[n], af, bf);
            }
        }
    }

    float i0 = 1.f / l0, i1 = 1.f / l1;
    float* Op = O + base + (size_t)(qrow + g) * Dmod;
    #pragma unroll
    for (int n = 0; n < 8; n++) {
        *(float2*)(Op + n*8 + tig*2)          = make_float2(oacc[n][0]*i0, oacc[n][1]*i0);
        *(float2*)(Op + 8*Dmod + n*8 + tig*2) = make_float2(oacc[n][2]*i1, oacc[n][3]*i1);
    }
}

// ---------------- LayerNorm(1024) + exact GELU, in place ----------------
__global__ __launch_bounds__(256) void ln_gelu_kernel(
    float* __restrict__ Hm, const float* __restrict__ gw, const float* __restrict__ bw)
{
    __shared__ float red1[8];
    __shared__ float red2[8];
    __shared__ float s_mu, s_inv;

    const int row = blockIdx.x;
    const int tid = threadIdx.x;
    float* hp = Hm + (size_t)row * FFd;

    float v[4];
    float s = 0.f;
    #pragma unroll
    for (int i = 0; i < 4; i++) { v[i] = hp[tid + i*256]; s += v[i]; }

    #pragma unroll
    for (int off = 16; off; off >>= 1) s += __shfl_xor_sync(0xffffffffu, s, off);
    if ((tid & 31) == 0) red1[tid >> 5] = s;
    __syncthreads();
    if (tid == 0) {
        float t = 0.f;
        #pragma unroll
        for (int w = 0; w < 8; w++) t += red1[w];
        s_mu = t * (1.f / FFd);
    }
    __syncthreads();
    const float mu = s_mu;

    float ss = 0.f;
    #pragma unroll
    for (int i = 0; i < 4; i++) { float d = v[i] - mu; ss += d*d; }
    #pragma unroll
    for (int off = 16; off; off >>= 1) ss += __shfl_xor_sync(0xffffffffu, ss, off);
    if ((tid & 31) == 0) red2[tid >> 5] = ss;
    __syncthreads();
    if (tid == 0) {
        float t = 0.f;
        #pragma unroll
        for (int w = 0; w < 8; w++) t += red2[w];
        s_inv = rsqrtf(t * (1.f / FFd) + 1e-5f);
    }
    __syncthreads();
    const float inv = s_inv;

    #pragma unroll
    for (int i = 0; i < 4; i++) {
        int c = tid + i*256;
        float x = (v[i] - mu) * inv * gw[c] + bw[c];
        hp[c] = 0.5f * x * (1.f + erff(x * 0.70710678118654752f));
    }
}

// ---------------- launcher ----------------
extern "C" void kernel_launch(void* const* d_in, const int* in_sizes, int n_in,
                              void* d_out, int out_size)
{
    const float* x0  = (const float*)d_in[0];
    const float* x1  = (const float*)d_in[1];
    const float* Wqk = (const float*)d_in[2];
    const float* bqk = (const float*)d_in[3];
    const float* Wv  = (const float*)d_in[4];
    const float* bv  = (const float*)d_in[5];
    const float* Wo  = (const float*)d_in[6];
    const float* bo  = (const float*)d_in[7];
    const float* Wf1 = (const float*)d_in[8];
    const float* bf1 = (const float*)d_in[9];
    const float* lng = (const float*)d_in[10];
    const float* lnb = (const float*)d_in[11];
    const float* Wf2 = (const float*)d_in[12];
    const float* bf2 = (const float*)d_in[13];
    float* out = (float*)d_out;

    float *qk0, *qk1, *v0, *v1, *a0, *a1, *hmid;
    cudaGetSymbolAddress((void**)&qk0,  g_qk0);
    cudaGetSymbolAddress((void**)&qk1,  g_qk1);
    cudaGetSymbolAddress((void**)&v0,   g_v0);
    cudaGetSymbolAddress((void**)&v1,   g_v1);
    cudaGetSymbolAddress((void**)&a0,   g_a0);
    cudaGetSymbolAddress((void**)&a1,   g_a1);
    cudaGetSymbolAddress((void**)&hmid, g_hmid);

    const int GSMEM = 65536;
    cudaFuncSetAttribute(gemm_tc<false>, cudaFuncAttributeMaxDynamicSharedMemorySize, GSMEM);
    cudaFuncSetAttribute(gemm_tc<true>,  cudaFuncAttributeMaxDynamicSharedMemorySize, GSMEM);
    cudaFuncSetAttribute(attn_tc, cudaFuncAttributeMaxDynamicSharedMemorySize, ATTN_SMEM);

    dim3 g512(Dmod/128, Mrows/128);   // (4, 64)
    dim3 g1024(FFd/128, Mrows/128);   // (8, 64)
    dim3 ga(Bsz*Hh, Nseq/128);        // (32, 16)

    // projections
    gemm_tc<false><<<g512, 256, GSMEM>>>(x0, nullptr, Wqk, bqk, nullptr, qk0, Mrows, Dmod, Dmod);
    gemm_tc<false><<<g512, 256, GSMEM>>>(x1, nullptr, Wqk, bqk, nullptr, qk1, Mrows, Dmod, Dmod);
    gemm_tc<false><<<g512, 256, GSMEM>>>(x0, nullptr, Wv,  bv,  nullptr, v0,  Mrows, Dmod, Dmod);
    gemm_tc<false><<<g512, 256, GSMEM>>>(x1, nullptr, Wv,  bv,  nullptr, v1,  Mrows, Dmod, Dmod);

    // cross attention
    attn_tc<<<ga, 256, ATTN_SMEM>>>(qk0, qk1, v1, a0);
    attn_tc<<<ga, 256, ATTN_SMEM>>>(qk1, qk0, v0, a1);

    // output projection (reuse v1/v0 as m0/m1)
    gemm_tc<false><<<g512, 256, GSMEM>>>(a0, nullptr, Wo, bo, nullptr, v1, Mrows, Dmod, Dmod);
    gemm_tc<false><<<g512, 256, GSMEM>>>(a1, nullptr, Wo, bo, nullptr, v0, Mrows, Dmod, Dmod);

    // FFN stream 0 (concat fused into FFN1 A-loader)
    gemm_tc<true><<<g1024, 256, GSMEM>>>(x0, v1, Wf1, bf1, nullptr, hmid, Mrows, FFd, FFd);
    ln_gelu_kernel<<<Mrows, 256>>>(hmid, lng, lnb);
    gemm_tc<false><<<g512, 256, GSMEM>>>(hmid, nullptr, Wf2, bf2, x0, out, Mrows, Dmod, FFd);

    // FFN stream 1
    gemm_tc<true><<<g1024, 256, GSMEM>>>(x1, v0, Wf1, bf1, nullptr, hmid, Mrows, FFd, FFd);
    ln_gelu_kernel<<<Mrows, 256>>>(hmid, lng, lnb);
    gemm_tc<false><<<g512, 256, GSMEM>>>(hmid, nullptr, Wf2, bf2, x1, out + (size_t)Mrows*Dmod, Mrows, Dmod, FFd);
}

// round 9
// speedup vs baseline: 1.7263x; 1.1604x over previous
#include <cuda_runtime.h>
#include <math.h>
#include <stdint.h>

#define Bsz  4
#define Nseq 2048
#define Dmod 512
#define Hh   8
#define DHd  64
#define FFd  1024
#define Mrows (Bsz*Nseq)   // 8192

// ---------------- scratch ----------------
__device__ float g_qk0[Mrows*Dmod];
__device__ float g_qk1[Mrows*Dmod];
__device__ float g_v0 [Mrows*Dmod];
__device__ float g_v1 [Mrows*Dmod];
__device__ float g_a0 [Mrows*Dmod];
__device__ float g_a1 [Mrows*Dmod];
__device__ float g_hmid[Mrows*FFd];

// ---------------- helpers ----------------
__device__ __forceinline__ void mma_tf32(float d[4], const uint32_t a[4], const uint32_t b[2]) {
    asm volatile(
        "mma.sync.aligned.m16n8k8.row.col.f32.tf32.tf32.f32 "
        "{%0,%1,%2,%3}, {%4,%5,%6,%7}, {%8,%9}, {%0,%1,%2,%3};\n"
        : "+f"(d[0]), "+f"(d[1]), "+f"(d[2]), "+f"(d[3])
        : "r"(a[0]), "r"(a[1]), "r"(a[2]), "r"(a[3]), "r"(b[0]), "r"(b[1]));
}
__device__ __forceinline__ void ldsm4(uint32_t r[4], uint32_t addr) {
    asm volatile("ldmatrix.sync.aligned.m8n8.x4.shared.b16 {%0,%1,%2,%3}, [%4];"
        : "=r"(r[0]), "=r"(r[1]), "=r"(r[2]), "=r"(r[3]) : "r"(addr));
}
#define CP16(dst, src) asm volatile("cp.async.cg.shared.global [%0], [%1], 16;\n" :: "r"(dst), "l"(src))
#define CPCOMMIT()     asm volatile("cp.async.commit_group;\n" ::: "memory")
#define CPWAIT(n)      asm volatile("cp.async.wait_group %0;\n" :: "n"(n) : "memory")

// float offset within a [rows][8 units of 16B] panel, XOR-swizzled (pitch 32 floats)
__device__ __forceinline__ int swz8(int row, int u) {
    return row * 32 + ((u ^ (row & 7)) << 2);
}

// ---------------- TF32 GEMM: cp.async 3-stage + ldmatrix ----------------
// C[M,N] = A[M,K]*W[N,K]^T + bias (+res). 128x128 tile, BK=32, 8 warps (2x4).
// CAT: A is virtual concat [A | A2], each M x 512 (requires K=1024).
// smem bytes: A stage s @ s*16384 ; B stage s @ 49152 + s*16384  (96 KB)
#define GSMEM 98304
template<bool CAT>
__global__ __launch_bounds__(256, 2) void gemm_tc(
    const float* __restrict__ A, const float* __restrict__ A2,
    const float* __restrict__ W,
    const float* __restrict__ bias, const float* __restrict__ res,
    float* __restrict__ C, int M, int N, int K)
{
    extern __shared__ float sm[];
    const uint32_t smB = (uint32_t)__cvta_generic_to_shared(sm);

    const int tid  = threadIdx.x;
    const int wid  = tid >> 5, lane = tid & 31;
    const int g    = lane >> 2, tig = lane & 3;
    const int wm   = wid & 1,  wn   = wid >> 1;
    const int lr   = tid >> 3;       // 0..31 (copy row base)
    const int lu   = tid & 7;        // copy unit
    const int j    = lane >> 3;      // ldmatrix matrix id
    const int jr   = (j & 1) * 8, jc = (j >> 1);
    const int l7   = lane & 7;

    const int arow0 = blockIdx.y * 128;
    const int brow0 = blockIdx.x * 128;

    // fragment row bases (bytes within a stage panel); row&7 == l7 for all
    uint32_t rbA[4], rbB[2];
    #pragma unroll
    for (int m = 0; m < 4; m++) rbA[m] = (uint32_t)(wm*64 + m*16 + jr + l7) * 128u;
    #pragma unroll
    for (int np = 0; np < 2; np++) rbB[np] = (uint32_t)(wn*32 + np*16 + jr + l7) * 128u;

    // copy destination base (bytes within a stage panel), swizzled
    const uint32_t cpOff = (uint32_t)swz8(lr, lu) * 4u;

    float acc[4][4][4];
    #pragma unroll
    for (int m = 0; m < 4; m++)
        #pragma unroll
        for (int n = 0; n < 4; n++)
            #pragma unroll
            for (int q = 0; q < 4; q++) acc[m][n][q] = 0.f;

    const int T = K / 32;

    auto issue = [&](int t, int s) {
        const int colg = t*32 + lu*4;
        const uint32_t dstA = smB + (uint32_t)s*16384u + cpOff;
        const uint32_t dstB = dstA + 49152u;
        #pragma unroll
        for (int i = 0; i < 4; i++) {
            int row = lr + 32*i;
            const float* srcA;
            if (CAT) {
                srcA = (colg < 512) ? (A  + (size_t)(arow0+row)*512 + colg)
                                    : (A2 + (size_t)(arow0+row)*512 + colg - 512);
            } else {
                srcA = A + (size_t)(arow0+row)*K + colg;
            }
            CP16(dstA + i*4096u, srcA);
            CP16(dstB + i*4096u, W + (size_t)(brow0+row)*K + colg);
        }
        CPCOMMIT();
    };

    issue(0, 0);
    issue(1, 1);
    int so = 0;

    for (int t = 0; t < T; t++) {
        if (t + 1 < T) { CPWAIT(1); } else { CPWAIT(0); }
        __syncthreads();
        if (t + 2 < T) {
            int s = so + 2;            // (t+2) % 3
            if (s >= 3) s -= 3;
            issue(t + 2, s);
        }

        const uint32_t sb = smB + (uint32_t)so * 16384u;
        #pragma unroll
        for (int kq = 0; kq < 4; kq++) {
            const uint32_t xofs = (uint32_t)((((kq << 1) | jc) ^ l7) << 4);
            uint32_t af[4][4], bf[4][2];
            #pragma unroll
            for (int m = 0; m < 4; m++)
                ldsm4(af[m], sb + rbA[m] + xofs);
            #pragma unroll
            for (int np = 0; np < 2; np++) {
                uint32_t t4[4];
                ldsm4(t4, sb + 49152u + rbB[np] + xofs);
                bf[2*np  ][0] = t4[0]; bf[2*np  ][1] = t4[2];
                bf[2*np+1][0] = t4[1]; bf[2*np+1][1] = t4[3];
            }
            #pragma unroll
            for (int m = 0; m < 4; m++)
                #pragma unroll
                for (int n = 0; n < 4; n++)
                    mma_tf32(acc[m][n], af[m], bf[n]);
        }
        so = (so == 2) ? 0 : so + 1;
    }

    const int rb = arow0 + wm * 64;
    const int cb = brow0 + wn * 32;
    #pragma unroll
    for (int m = 0; m < 4; m++) {
        #pragma unroll
        for (int n = 0; n < 4; n++) {
            int row0 = rb + m*16 + g;
            int col  = cb + n*8 + tig*2;
            float b0 = bias[col], b1 = bias[col+1];
            float v0 = acc[m][n][0] + b0, v1 = acc[m][n][1] + b1;
            float v2 = acc[m][n][2] + b0, v3 = acc[m][n][3] + b1;
            if (res) {
                const float* r0p = res + (size_t)row0 * N + col;
                const float* r1p = res + (size_t)(row0+8) * N + col;
                v0 += r0p[0]; v1 += r0p[1];
                v2 += r1p[0]; v3 += r1p[1];
            }
            *(float2*)(C + (size_t)row0     * N + col) = make_float2(v0, v1);
            *(float2*)(C + (size_t)(row0+8) * N + col) = make_float2(v2, v3);
        }
    }
}

// ---------------- Flash attention: cp.async 2-stage K/V, tf32 mma ----------------
// smem floats: K stage s @ s*4352 ; V stage s @ 8704 + s*4352 ; P @ 17408 (128x68)
#define KT 64
#define ATTN_SMEM ((17408 + 128*68) * 4)   // 104448 bytes

__global__ __launch_bounds__(256) void attn_tc(
    const float* __restrict__ Q, const float* __restrict__ Kt,
    const float* __restrict__ V, float* __restrict__ O)
{
    extern __shared__ float smbuf[];
    const uint32_t smB = (uint32_t)__cvta_generic_to_shared(smbuf);
    float (*Ps)[68] = (float(*)[68])(smbuf + 17408);

    const int tid  = threadIdx.x;
    const int wid  = tid >> 5, lane = tid & 31;
    const int g    = lane >> 2, tig = lane & 3;

    const int bh = blockIdx.x;
    const int b  = bh >> 3, h = bh & 7;
    const size_t base = (size_t)b * (Nseq * Dmod) + (size_t)h * DHd;
    const int qrow = blockIdx.y * 128 + wid * 16;

    uint32_t qf[8][4];
    {
        const float* qp = Q + base + (size_t)(qrow + g) * Dmod;
        #pragma unroll
        for (int ks = 0; ks < 8; ks++) {
            qf[ks][0] = __float_as_uint(qp[ks*8 + tig]);
            qf[ks][1] = __float_as_uint(qp[8*Dmod + ks*8 + tig]);
            qf[ks][2] = __float_as_uint(qp[ks*8 + tig + 4]);
            qf[ks][3] = __float_as_uint(qp[8*Dmod + ks*8 + tig + 4]);
        }
    }

    float oacc[8][4];
    #pragma unroll
    for (int n = 0; n < 8; n++)
        #pragma unroll
        for (int q = 0; q < 4; q++) oacc[n][q] = 0.f;
    float m0 = -1e30f, m1 = -1e30f, l0 = 0.f, l1 = 0.f;

    const int lr = tid >> 2;
    const int lc = (tid & 3) * 4;
    const float* Kg = Kt + base + (size_t)lr * Dmod + lc;
    const float* Vg = V  + base + (size_t)lr * Dmod + lc;
    const int pr = wid * 16 + g;

    const uint32_t kvOff = (uint32_t)(lr * 68 + lc) * 4u;
    auto issueKV = [&](int kt) {
        const int s = kt & 1;
        const size_t off = (size_t)kt * KT * Dmod;
        const uint32_t kd = smB + (uint32_t)s * 17408u + kvOff;
        const uint32_t vd = kd + 34816u;
        #pragma unroll
        for (int i = 0; i < 4; i++) {
            CP16(kd + i*64u, Kg + off + 16*i);
            CP16(vd + i*64u, Vg + off + 16*i);
        }
        CPCOMMIT();
    };

    issueKV(0);
    const int TKT = Nseq / KT;
    for (int kt = 0; kt < TKT; kt++) {
        if (kt + 1 < TKT) { issueKV(kt + 1); CPWAIT(1); } else { CPWAIT(0); }
        __syncthreads();

        float (*Ks)[68] = (float(*)[68])(smbuf + (kt & 1) * 4352);
        float (*Vs)[68] = (float(*)[68])(smbuf + 8704 + (kt & 1) * 4352);

        float sacc[8][4];
        #pragma unroll
        for (int n = 0; n < 8; n++)
            #pragma unroll
            for (int q = 0; q < 4; q++) sacc[n][q] = 0.f;

        #pragma unroll
        for (int ks = 0; ks < 8; ks++) {
            uint32_t bf[8][2];
            #pragma unroll
            for (int n = 0; n < 8; n++) {
                bf[n][0] = __float_as_uint(Ks[n*8 + g][ks*8 + tig]);
                bf[n][1] = __float_as_uint(Ks[n*8 + g][ks*8 + tig + 4]);
            }
            #pragma unroll
            for (int n = 0; n < 8; n++) mma_tf32(sacc[n], qf[ks], bf[n]);
        }

        float t0 = -1e30f, t1 = -1e30f;
        #pragma unroll
        for (int n = 0; n < 8; n++) {
            sacc[n][0] *= 0.125f; sacc[n][1] *= 0.125f;
            sacc[n][2] *= 0.125f; sacc[n][3] *= 0.125f;
            t0 = fmaxf(t0, fmaxf(sacc[n][0], sacc[n][1]));
            t1 = fmaxf(t1, fmaxf(sacc[n][2], sacc[n][3]));
        }
        t0 = fmaxf(t0, __shfl_xor_sync(0xffffffffu, t0, 1));
        t0 = fmaxf(t0, __shfl_xor_sync(0xffffffffu, t0, 2));
        t1 = fmaxf(t1, __shfl_xor_sync(0xffffffffu, t1, 1));
        t1 = fmaxf(t1, __shfl_xor_sync(0xffffffffu, t1, 2));

        float mn0 = fmaxf(m0, t0), mn1 = fmaxf(m1, t1);
        float c0 = __expf(m0 - mn0), c1 = __expf(m1 - mn1);
        m0 = mn0; m1 = mn1;

        float ps0 = 0.f, ps1 = 0.f;
        #pragma unroll
        for (int n = 0; n < 8; n++) {
            float p00 = __expf(sacc[n][0] - m0), p01 = __expf(sacc[n][1] - m0);
            float p10 = __expf(sacc[n][2] - m1), p11 = __expf(sacc[n][3] - m1);
            ps0 += p00 + p01; ps1 += p10 + p11;
            sacc[n][0] = p00; sacc[n][1] = p01; sacc[n][2] = p10; sacc[n][3] = p11;
        }
        ps0 += __shfl_xor_sync(0xffffffffu, ps0, 1);
        ps0 += __shfl_xor_sync(0xffffffffu, ps0, 2);
        ps1 += __shfl_xor_sync(0xffffffffu, ps1, 1);
        ps1 += __shfl_xor_sync(0xffffffffu, ps1, 2);
        l0 = l0 * c0 + ps0;
        l1 = l1 * c1 + ps1;
        #pragma unroll
        for (int n = 0; n < 8; n++) {
            oacc[n][0] *= c0; oacc[n][1] *= c0;
            oacc[n][2] *= c1; oacc[n][3] *= c1;
        }

        // P tile: warp-private rows -> only warp-level sync needed
        #pragma unroll
        for (int n = 0; n < 8; n++) {
            Ps[pr    ][n*8 + tig*2    ] = sacc[n][0];
            Ps[pr    ][n*8 + tig*2 + 1] = sacc[n][1];
            Ps[pr + 8][n*8 + tig*2    ] = sacc[n][2];
            Ps[pr + 8][n*8 + tig*2 + 1] = sacc[n][3];
        }
        __syncwarp();

        #pragma unroll
        for (int ks = 0; ks < 8; ks++) {
            uint32_t af[4];
            af[0] = __float_as_uint(Ps[pr    ][ks*8 + tig]);
            af[1] = __float_as_uint(Ps[pr + 8][ks*8 + tig]);
            af[2] = __float_as_uint(Ps[pr    ][ks*8 + tig + 4]);
            af[3] = __float_as_uint(Ps[pr + 8][ks*8 + tig + 4]);
            #pragma unroll
            for (int n = 0; n < 8; n++) {
                uint32_t bf[2];
                bf[0] = __float_as_uint(Vs[ks*8 + tig    ][n*8 + g]);
                bf[1] = __float_as_uint(Vs[ks*8 + tig + 4][n*8 + g]);
                mma_tf32(oacc[n], af, bf);
            }
        }
        __syncthreads();   // all warps done with stage (kt&1) before it is overwritten
    }

    float i0 = 1.f / l0, i1 = 1.f / l1;
    float* Op = O + base + (size_t)(qrow + g) * Dmod;
    #pragma unroll
    for (int n = 0; n < 8; n++) {
        *(float2*)(Op + n*8 + tig*2)          = make_float2(oacc[n][0]*i0, oacc[n][1]*i0);
        *(float2*)(Op + 8*Dmod + n*8 + tig*2) = make_float2(oacc[n][2]*i1, oacc[n][3]*i1);
    }
}

// ---------------- LayerNorm(1024) + exact GELU, in place ----------------
__global__ __launch_bounds__(256) void ln_gelu_kernel(
    float* __restrict__ Hm, const float* __restrict__ gw, const float* __restrict__ bw)
{
    __shared__ float red1[8];
    __shared__ float red2[8];
    __shared__ float s_mu, s_inv;

    const int row = blockIdx.x;
    const int tid = threadIdx.x;
    float* hp = Hm + (size_t)row * FFd;

    float v[4];
    float s = 0.f;
    #pragma unroll
    for (int i = 0; i < 4; i++) { v[i] = hp[tid + i*256]; s += v[i]; }

    #pragma unroll
    for (int off = 16; off; off >>= 1) s += __shfl_xor_sync(0xffffffffu, s, off);
    if ((tid & 31) == 0) red1[tid >> 5] = s;
    __syncthreads();
    if (tid == 0) {
        float t = 0.f;
        #pragma unroll
        for (int w = 0; w < 8; w++) t += red1[w];
        s_mu = t * (1.f / FFd);
    }
    __syncthreads();
    const float mu = s_mu;

    float ss = 0.f;
    #pragma unroll
    for (int i = 0; i < 4; i++) { float d = v[i] - mu; ss += d*d; }
    #pragma unroll
    for (int off = 16; off; off >>= 1) ss += __shfl_xor_sync(0xffffffffu, ss, off);
    if ((tid & 31) == 0) red2[tid >> 5] = ss;
    __syncthreads();
    if (tid == 0) {
        float t = 0.f;
        #pragma unroll
        for (int w = 0; w < 8; w++) t += red2[w];
        s_inv = rsqrtf(t * (1.f / FFd) + 1e-5f);
    }
    __syncthreads();
    const float inv = s_inv;

    #pragma unroll
    for (int i = 0; i < 4; i++) {
        int c = tid + i*256;
        float x = (v[i] - mu) * inv * gw[c] + bw[c];
        hp[c] = 0.5f * x * (1.f + erff(x * 0.70710678118654752f));
    }
}

// ---------------- launcher ----------------
extern "C" void kernel_launch(void* const* d_in, const int* in_sizes, int n_in,
                              void* d_out, int out_size)
{
    const float* x0  = (const float*)d_in[0];
    const float* x1  = (const float*)d_in[1];
    const float* Wqk = (const float*)d_in[2];
    const float* bqk = (const float*)d_in[3];
    const float* Wv  = (const float*)d_in[4];
    const float* bv  = (const float*)d_in[5];
    const float* Wo  = (const float*)d_in[6];
    const float* bo  = (const float*)d_in[7];
    const float* Wf1 = (const float*)d_in[8];
    const float* bf1 = (const float*)d_in[9];
    const float* lng = (const float*)d_in[10];
    const float* lnb = (const float*)d_in[11];
    const float* Wf2 = (const float*)d_in[12];
    const float* bf2 = (const float*)d_in[13];
    float* out = (float*)d_out;

    float *qk0, *qk1, *v0, *v1, *a0, *a1, *hmid;
    cudaGetSymbolAddress((void**)&qk0,  g_qk0);
    cudaGetSymbolAddress((void**)&qk1,  g_qk1);
    cudaGetSymbolAddress((void**)&v0,   g_v0);
    cudaGetSymbolAddress((void**)&v1,   g_v1);
    cudaGetSymbolAddress((void**)&a0,   g_a0);
    cudaGetSymbolAddress((void**)&a1,   g_a1);
    cudaGetSymbolAddress((void**)&hmid, g_hmid);

    cudaFuncSetAttribute(gemm_tc<false>, cudaFuncAttributeMaxDynamicSharedMemorySize, GSMEM);
    cudaFuncSetAttribute(gemm_tc<true>,  cudaFuncAttributeMaxDynamicSharedMemorySize, GSMEM);
    cudaFuncSetAttribute(attn_tc, cudaFuncAttributeMaxDynamicSharedMemorySize, ATTN_SMEM);

    dim3 g512(Dmod/128, Mrows/128);   // (4, 64)
    dim3 g1024(FFd/128, Mrows/128);   // (8, 64)
    dim3 ga(Bsz*Hh, Nseq/128);        // (32, 16)

    // projections
    gemm_tc<false><<<g512, 256, GSMEM>>>(x0, nullptr, Wqk, bqk, nullptr, qk0, Mrows, Dmod, Dmod);
    gemm_tc<false><<<g512, 256, GSMEM>>>(x1, nullptr, Wqk, bqk, nullptr, qk1, Mrows, Dmod, Dmod);
    gemm_tc<false><<<g512, 256, GSMEM>>>(x0, nullptr, Wv,  bv,  nullptr, v0,  Mrows, Dmod, Dmod);
    gemm_tc<false><<<g512, 256, GSMEM>>>(x1, nullptr, Wv,  bv,  nullptr, v1,  Mrows, Dmod, Dmod);

    // cross attention
    attn_tc<<<ga, 256, ATTN_SMEM>>>(qk0, qk1, v1, a0);
    attn_tc<<<ga, 256, ATTN_SMEM>>>(qk1, qk0, v0, a1);

    // output projection (reuse v1/v0 as m0/m1)
    gemm_tc<false><<<g512, 256, GSMEM>>>(a0, nullptr, Wo, bo, nullptr, v1, Mrows, Dmod, Dmod);
    gemm_tc<false><<<g512, 256, GSMEM>>>(a1, nullptr, Wo, bo, nullptr, v0, Mrows, Dmod, Dmod);

    // FFN stream 0 (concat fused into FFN1 A-loader)
    gemm_tc<true><<<g1024, 256, GSMEM>>>(x0, v1, Wf1, bf1, nullptr, hmid, Mrows, FFd, FFd);
    ln_gelu_kernel<<<Mrows, 256>>>(hmid, lng, lnb);
    gemm_tc<false><<<g512, 256, GSMEM>>>(hmid, nullptr, Wf2, bf2, x0, out, Mrows, Dmod, FFd);

    // FFN stream 1
    gemm_tc<true><<<g1024, 256, GSMEM>>>(x1, v0, Wf1, bf1, nullptr, hmid, Mrows, FFd, FFd);
    ln_gelu_kernel<<<Mrows, 256>>>(hmid, lng, lnb);
    gemm_tc<false><<<g512, 256, GSMEM>>>(hmid, nullptr, Wf2, bf2, x1, out + (size_t)Mrows*Dmod, Mrows, Dmod, FFd);
}

// round 12
// speedup vs baseline: 3.1562x; 1.8283x over previous
#include <cuda_runtime.h>
#include <cuda_fp16.h>
#include <math.h>
#include <stdint.h>

#define Bsz  4
#define Nseq 2048
#define Dmod 512
#define Hh   8
#define DHd  64
#define FFd  1024
#define Mrows (Bsz*Nseq)   // 8192

// ---------------- fp16 scratch ----------------
__device__ __half g_hx0 [Mrows*Dmod];
__device__ __half g_hx1 [Mrows*Dmod];
__device__ __half g_hqk0[Mrows*Dmod];
__device__ __half g_hqk1[Mrows*Dmod];
__device__ __half g_hv0 [Mrows*Dmod];
__device__ __half g_hv1 [Mrows*Dmod];
__device__ __half g_ha0 [Mrows*Dmod];
__device__ __half g_ha1 [Mrows*Dmod];
__device__ __half g_hm0 [Mrows*Dmod];
__device__ __half g_hm1 [Mrows*Dmod];
__device__ __half g_hmid[Mrows*FFd];
__device__ __half g_hwqk[Dmod*Dmod];
__device__ __half g_hwv [Dmod*Dmod];
__device__ __half g_hwo [Dmod*Dmod];
__device__ __half g_hwf1[FFd*FFd];
__device__ __half g_hwf2[Dmod*FFd];

// ---------------- helpers ----------------
__device__ __forceinline__ void mma_f16(float d[4], const uint32_t a[4], const uint32_t b[2]) {
    asm volatile(
        "mma.sync.aligned.m16n8k16.row.col.f32.f16.f16.f32 "
        "{%0,%1,%2,%3}, {%4,%5,%6,%7}, {%8,%9}, {%0,%1,%2,%3};\n"
        : "+f"(d[0]), "+f"(d[1]), "+f"(d[2]), "+f"(d[3])
        : "r"(a[0]), "r"(a[1]), "r"(a[2]), "r"(a[3]), "r"(b[0]), "r"(b[1]));
}
__device__ __forceinline__ void ldsm4(uint32_t r[4], uint32_t addr) {
    asm volatile("ldmatrix.sync.aligned.m8n8.x4.shared.b16 {%0,%1,%2,%3}, [%4];"
        : "=r"(r[0]), "=r"(r[1]), "=r"(r[2]), "=r"(r[3]) : "r"(addr));
}
__device__ __forceinline__ void ldsm4t(uint32_t r[4], uint32_t addr) {
    asm volatile("ldmatrix.sync.aligned.m8n8.x4.trans.shared.b16 {%0,%1,%2,%3}, [%4];"
        : "=r"(r[0]), "=r"(r[1]), "=r"(r[2]), "=r"(r[3]) : "r"(addr));
}
#define CP16(dst, src) asm volatile("cp.async.cg.shared.global [%0], [%1], 16;\n" :: "r"(dst), "l"(src))
#define CPCOMMIT()     asm volatile("cp.async.commit_group;\n" ::: "memory")
#define CPWAIT(n)      asm volatile("cp.async.wait_group %0;\n" :: "n"(n) : "memory")

// ---------------- f32 -> f16 conversion ----------------
__global__ void f2h_kernel(const float* __restrict__ s, __half* __restrict__ d, int n) {
    int i = (blockIdx.x * blockDim.x + threadIdx.x) * 4;
    if (i < n) {
        float4 v = *(const float4*)(s + i);
        __half2* dp = (__half2*)(d + i);
        dp[0] = __floats2half2_rn(v.x, v.y);
        dp[1] = __floats2half2_rn(v.z, v.w);
    }
}

// ---------------- FP16 GEMM: cp.async 3-stage + ldmatrix, m16n8k16 ----------------
// C[M,N] = A[M,K]*W[N,K]^T + bias (+res when fp32 out). 128x128 tile, BK=64.
// 8 warps (2x4). smem bytes: stage s: A @ s*32768, B @ s*32768+16384. (96 KB)
#define GSMEM 98304
template<bool CAT, bool OUTH>
__global__ __launch_bounds__(256, 2) void gemm_h(
    const __half* __restrict__ A, const __half* __restrict__ A2,
    const __half* __restrict__ W,
    const float* __restrict__ bias, const float* __restrict__ res,
    float* __restrict__ Cf, __half* __restrict__ Ch, int M, int N, int K)
{
    extern __shared__ float sm[];
    const uint32_t smB = (uint32_t)__cvta_generic_to_shared(sm);

    const int tid  = threadIdx.x;
    const int wid  = tid >> 5, lane = tid & 31;
    const int g    = lane >> 2, tig = lane & 3;
    const int wm   = wid & 1,  wn   = wid >> 1;
    const int lr   = tid >> 3;       // copy row base 0..31
    const int lu   = tid & 7;        // copy unit
    const int j    = lane >> 3;      // ldmatrix matrix id
    const int jr   = (j & 1) * 8, jc = (j >> 1);
    const int l7   = lane & 7;

    const int arow0 = blockIdx.y * 128;
    const int brow0 = blockIdx.x * 128;

    uint32_t rbA[4], rbB[2];
    #pragma unroll
    for (int m = 0; m < 4; m++) rbA[m] = (uint32_t)(wm*64 + m*16 + jr + l7) * 128u;
    #pragma unroll
    for (int np = 0; np < 2; np++) rbB[np] = (uint32_t)(wn*32 + np*16 + jr + l7) * 128u;

    const uint32_t cpOff = (uint32_t)(lr * 128 + ((lu ^ (lr & 7)) << 4));

    float acc[4][4][4];
    #pragma unroll
    for (int m = 0; m < 4; m++)
        #pragma unroll
        for (int n = 0; n < 4; n++)
            #pragma unroll
            for (int q = 0; q < 4; q++) acc[m][n][q] = 0.f;

    const int T = K / 64;

    auto issue = [&](int t, int s) {
        const int colg = t*64 + lu*8;      // fp16 elements
        const uint32_t dstA = smB + (uint32_t)s*32768u + cpOff;
        const uint32_t dstB = dstA + 16384u;
        #pragma unroll
        for (int i = 0; i < 4; i++) {
            int row = lr + 32*i;
            const __half* srcA;
            if (CAT) {
                srcA = (colg < 512) ? (A  + (size_t)(arow0+row)*512 + colg)
                                    : (A2 + (size_t)(arow0+row)*512 + colg - 512);
            } else {
                srcA = A + (size_t)(arow0+row)*K + colg;
            }
            CP16(dstA + i*4096u, srcA);
            CP16(dstB + i*4096u, W + (size_t)(brow0+row)*K + colg);
        }
        CPCOMMIT();
    };

    issue(0, 0);
    issue(1, 1);
    int so = 0;

    for (int t = 0; t < T; t++) {
        if (t + 1 < T) { CPWAIT(1); } else { CPWAIT(0); }
        __syncthreads();
        if (t + 2 < T) {
            int s = so + 2;
            if (s >= 3) s -= 3;
            issue(t + 2, s);
        }

        const uint32_t aB = smB + (uint32_t)so * 32768u;
        const uint32_t bB = aB + 16384u;

        #pragma unroll
        for (int kk = 0; kk < 4; kk++) {
            const uint32_t xofs = (uint32_t)((((kk << 1) | jc) ^ l7) << 4);
            uint32_t af[4][4], bf[4][2];
            #pragma unroll
            for (int m = 0; m < 4; m++)
                ldsm4(af[m], aB + rbA[m] + xofs);
            #pragma unroll
            for (int np = 0; np < 2; np++) {
                uint32_t t4[4];
                ldsm4(t4, bB + rbB[np] + xofs);
                bf[2*np  ][0] = t4[0]; bf[2*np  ][1] = t4[2];
                bf[2*np+1][0] = t4[1]; bf[2*np+1][1] = t4[3];
            }
            #pragma unroll
            for (int m = 0; m < 4; m++)
                #pragma unroll
                for (int n = 0; n < 4; n++)
                    mma_f16(acc[m][n], af[m], bf[n]);
        }
        so = (so == 2) ? 0 : so + 1;
    }

    const int rb = arow0 + wm * 64;
    const int cb = brow0 + wn * 32;
    #pragma unroll
    for (int m = 0; m < 4; m++) {
        #pragma unroll
        for (int n = 0; n < 4; n++) {
            int row0 = rb + m*16 + g;
            int col  = cb + n*8 + tig*2;
            float b0 = bias[col], b1 = bias[col+1];
            float v0 = acc[m][n][0] + b0, v1 = acc[m][n][1] + b1;
            float v2 = acc[m][n][2] + b0, v3 = acc[m][n][3] + b1;
            if (OUTH) {
                *(__half2*)(Ch + (size_t)row0     * N + col) = __floats2half2_rn(v0, v1);
                *(__half2*)(Ch + (size_t)(row0+8) * N + col) = __floats2half2_rn(v2, v3);
            } else {
                if (res) {
                    const float* r0p = res + (size_t)row0 * N + col;
                    const float* r1p = res + (size_t)(row0+8) * N + col;
                    v0 += r0p[0]; v1 += r0p[1];
                    v2 += r1p[0]; v3 += r1p[1];
                }
                *(float2*)(Cf + (size_t)row0     * N + col) = make_float2(v0, v1);
                *(float2*)(Cf + (size_t)(row0+8) * N + col) = make_float2(v2, v3);
            }
        }
    }
}

// ---------------- FP16 flash attention ----------------
// 256 thr / 8 warps, 128 q-rows per block, key tiles of 64, 2-stage cp.async.
// smem bytes: stage s: K @ s*16384, V @ s*16384+8192 ; P @ 32768 (128 rows x 128B, swizzled)
#define KT 64
#define ATTN_SMEM 49152

__global__ __launch_bounds__(256) void attn_h(
    const __half* __restrict__ Q, const __half* __restrict__ Kt,
    const __half* __restrict__ V, __half* __restrict__ O)
{
    extern __shared__ float smbuf[];
    const uint32_t smB = (uint32_t)__cvta_generic_to_shared(smbuf);
    char* smc = (char*)smbuf;

    const int tid  = threadIdx.x;
    const int wid  = tid >> 5, lane = tid & 31;
    const int g    = lane >> 2, tig = lane & 3;
    const int j    = lane >> 3;
    const int jr   = (j & 1) * 8, jc = (j >> 1);
    const int l7   = lane & 7;

    const int bh = blockIdx.x;
    const int b  = bh >> 3, h = bh & 7;
    const size_t base = (size_t)b * (Nseq * Dmod) + (size_t)h * DHd;
    const int qrow = blockIdx.y * 128 + wid * 16;

    // Q fragments: 4 ksteps (k16) x 4 regs, from gmem fp16
    uint32_t qf[4][4];
    {
        const __half* qp = Q + base + (size_t)(qrow + g) * Dmod;
        #pragma unroll
        for (int ks = 0; ks < 4; ks++) {
            qf[ks][0] = *(const uint32_t*)(qp + ks*16 + tig*2);
            qf[ks][1] = *(const uint32_t*)(qp + 8*Dmod + ks*16 + tig*2);
            qf[ks][2] = *(const uint32_t*)(qp + ks*16 + 8 + tig*2);
            qf[ks][3] = *(const uint32_t*)(qp + 8*Dmod + ks*16 + 8 + tig*2);
        }
    }

    float oacc[8][4];
    #pragma unroll
    for (int n = 0; n < 8; n++)
        #pragma unroll
        for (int q = 0; q < 4; q++) oacc[n][q] = 0.f;
    float m0 = -1e30f, m1 = -1e30f, l0 = 0.f, l1 = 0.f;

    const int lr = tid >> 3;          // 0..31 copy row
    const int lu = tid & 7;           // copy unit
    const __half* Kg = Kt + base + (size_t)lr * Dmod + lu*8;
    const __half* Vg = V  + base + (size_t)lr * Dmod + lu*8;
    const int pr = wid * 16 + g;

    const uint32_t kvOff = (uint32_t)(lr * 128 + ((lu ^ (lr & 7)) << 4));
    auto issueKV = [&](int kt) {
        const int s = kt & 1;
        const size_t off = (size_t)kt * KT * Dmod;
        const uint32_t kd = smB + (uint32_t)s * 16384u + kvOff;
        const uint32_t vd = kd + 8192u;
        CP16(kd,          Kg + off);
        CP16(kd + 4096u,  Kg + off + 32*Dmod);
        CP16(vd,          Vg + off);
        CP16(vd + 4096u,  Vg + off + 32*Dmod);
        CPCOMMIT();
    };

    const uint32_t rbP = (uint32_t)(wid*16 + jr + l7) * 128u;

    issueKV(0);
    const int TKT = Nseq / KT;
    for (int kt = 0; kt < TKT; kt++) {
        if (kt + 1 < TKT) { issueKV(kt + 1); CPWAIT(1); } else { CPWAIT(0); }
        __syncthreads();

        const uint32_t Kst = smB + (uint32_t)(kt & 1) * 16384u;
        const uint32_t Vst = Kst + 8192u;

        // S = Q K^T : K smem [key][dh], non-trans ldsm (n=keys rows, k=dh contiguous)
        float sacc[8][4];
        #pragma unroll
        for (int n = 0; n < 8; n++)
            #pragma unroll
            for (int q = 0; q < 4; q++) sacc[n][q] = 0.f;

        #pragma unroll
        for (int kk = 0; kk < 4; kk++) {
            const uint32_t xofs = (uint32_t)((((kk << 1) | jc) ^ l7) << 4);
            uint32_t bf[8][2];
            #pragma unroll
            for (int p = 0; p < 4; p++) {
                uint32_t t4[4];
                ldsm4(t4, Kst + (uint32_t)((p*16 + jr + l7) * 128) + xofs);
                bf[2*p  ][0] = t4[0]; bf[2*p  ][1] = t4[2];
                bf[2*p+1][0] = t4[1]; bf[2*p+1][1] = t4[3];
            }
            #pragma unroll
            for (int n = 0; n < 8; n++) mma_f16(sacc[n], qf[kk], bf[n]);
        }

        // online softmax
        float t0 = -1e30f, t1 = -1e30f;
        #pragma unroll
        for (int n = 0; n < 8; n++) {
            sacc[n][0] *= 0.125f; sacc[n][1] *= 0.125f;
            sacc[n][2] *= 0.125f; sacc[n][3] *= 0.125f;
            t0 = fmaxf(t0, fmaxf(sacc[n][0], sacc[n][1]));
            t1 = fmaxf(t1, fmaxf(sacc[n][2], sacc[n][3]));
        }
        t0 = fmaxf(t0, __shfl_xor_sync(0xffffffffu, t0, 1));
        t0 = fmaxf(t0, __shfl_xor_sync(0xffffffffu, t0, 2));
        t1 = fmaxf(t1, __shfl_xor_sync(0xffffffffu, t1, 1));
        t1 = fmaxf(t1, __shfl_xor_sync(0xffffffffu, t1, 2));

        float mn0 = fmaxf(m0, t0), mn1 = fmaxf(m1, t1);
        float c0 = __expf(m0 - mn0), c1 = __expf(m1 - mn1);
        m0 = mn0; m1 = mn1;

        float ps0 = 0.f, ps1 = 0.f;
        #pragma unroll
        for (int n = 0; n < 8; n++) {
            float p00 = __expf(sacc[n][0] - m0), p01 = __expf(sacc[n][1] - m0);
            float p10 = __expf(sacc[n][2] - m1), p11 = __expf(sacc[n][3] - m1);
            ps0 += p00 + p01; ps1 += p10 + p11;
            sacc[n][0] = p00; sacc[n][1] = p01; sacc[n][2] = p10; sacc[n][3] = p11;
        }
        ps0 += __shfl_xor_sync(0xffffffffu, ps0, 1);
        ps0 += __shfl_xor_sync(0xffffffffu, ps0, 2);
        ps1 += __shfl_xor_sync(0xffffffffu, ps1, 1);
        ps1 += __shfl_xor_sync(0xffffffffu, ps1, 2);
        l0 = l0 * c0 + ps0;
        l1 = l1 * c1 + ps1;
        #pragma unroll
        for (int n = 0; n < 8; n++) {
            oacc[n][0] *= c0; oacc[n][1] *= c0;
            oacc[n][2] *= c1; oacc[n][3] *= c1;
        }

        // P -> smem as fp16 (swizzled, warp-private rows)
        #pragma unroll
        for (int n = 0; n < 8; n++) {
            uint32_t po = 32768u + (uint32_t)(pr * 128) + (uint32_t)(((n ^ g) << 4) + tig*4);
            *(__half2*)(smc + po)        = __floats2half2_rn(sacc[n][0], sacc[n][1]);
            *(__half2*)(smc + po + 1024) = __floats2half2_rn(sacc[n][2], sacc[n][3]);  // row pr+8
        }
        __syncwarp();

        // O += P V : P via ldsm (A), V via ldsm.trans (B), V smem [key][dh]
        #pragma unroll
        for (int ks = 0; ks < 4; ks++) {
            uint32_t af[4];
            ldsm4(af, smB + 32768u + rbP + (uint32_t)((((ks << 1) | jc) ^ l7) << 4));
            const uint32_t vrow = (uint32_t)((ks*16 + jr + l7) * 128);
            #pragma unroll
            for (int p = 0; p < 4; p++) {
                uint32_t t4[4];
                ldsm4t(t4, Vst + vrow + (uint32_t)((((p << 1) | jc) ^ l7) << 4));
                uint32_t bv0[2] = { t4[0], t4[1] };
                uint32_t bv1[2] = { t4[2], t4[3] };
                mma_f16(oacc[2*p  ], af, bv0);
                mma_f16(oacc[2*p+1], af, bv1);
            }
        }
        __syncthreads();
    }

    float i0 = 1.f / l0, i1 = 1.f / l1;
    __half* Op = O + base + (size_t)(qrow + g) * Dmod;
    #pragma unroll
    for (int n = 0; n < 8; n++) {
        *(__half2*)(Op + n*8 + tig*2)          = __floats2half2_rn(oacc[n][0]*i0, oacc[n][1]*i0);
        *(__half2*)(Op + 8*Dmod + n*8 + tig*2) = __floats2half2_rn(oacc[n][2]*i1, oacc[n][3]*i1);
    }
}

// ---------------- LayerNorm(1024) + exact GELU, fp16 in place ----------------
__global__ __launch_bounds__(256) void ln_gelu_h(
    __half* __restrict__ Hm, const float* __restrict__ gw, const float* __restrict__ bw)
{
    __shared__ float red1[8];
    __shared__ float red2[8];
    __shared__ float s_mu, s_inv;

    const int row = blockIdx.x;
    const int tid = threadIdx.x;
    __half* hp = Hm + (size_t)row * FFd;

    float v[4];
    float s = 0.f;
    #pragma unroll
    for (int i = 0; i < 4; i++) { v[i] = __half2float(hp[tid + i*256]); s += v[i]; }

    #pragma unroll
    for (int off = 16; off; off >>= 1) s += __shfl_xor_sync(0xffffffffu, s, off);
    if ((tid & 31) == 0) red1[tid >> 5] = s;
    __syncthreads();
    if (tid == 0) {
        float t = 0.f;
        #pragma unroll
        for (int w = 0; w < 8; w++) t += red1[w];
        s_mu = t * (1.f / FFd);
    }
    __syncthreads();
    const float mu = s_mu;

    float ss = 0.f;
    #pragma unroll
    for (int i = 0; i < 4; i++) { float d = v[i] - mu; ss += d*d; }
    #pragma unroll
    for (int off = 16; off; off >>= 1) ss += __shfl_xor_sync(0xffffffffu, ss, off);
    if ((tid & 31) == 0) red2[tid >> 5] = ss;
    __syncthreads();
    if (tid == 0) {
        float t = 0.f;
        #pragma unroll
        for (int w = 0; w < 8; w++) t += red2[w];
        s_inv = rsqrtf(t * (1.f / FFd) + 1e-5f);
    }
    __syncthreads();
    const float inv = s_inv;

    #pragma unroll
    for (int i = 0; i < 4; i++) {
        int c = tid + i*256;
        float x = (v[i] - mu) * inv * gw[c] + bw[c];
        hp[c] = __float2half_rn(0.5f * x * (1.f + erff(x * 0.70710678118654752f)));
    }
}

// ---------------- launcher ----------------
extern "C" void kernel_launch(void* const* d_in, const int* in_sizes, int n_in,
                              void* d_out, int out_size)
{
    const float* x0  = (const float*)d_in[0];
    const float* x1  = (const float*)d_in[1];
    const float* Wqk = (const float*)d_in[2];
    const float* bqk = (const float*)d_in[3];
    const float* Wv  = (const float*)d_in[4];
    const float* bv  = (const float*)d_in[5];
    const float* Wo  = (const float*)d_in[6];
    const float* bo  = (const float*)d_in[7];
    const float* Wf1 = (const float*)d_in[8];
    const float* bf1 = (const float*)d_in[9];
    const float* lng = (const float*)d_in[10];
    const float* lnb = (const float*)d_in[11];
    const float* Wf2 = (const float*)d_in[12];
    const float* bf2 = (const float*)d_in[13];
    float* out = (float*)d_out;

    __half *hx0, *hx1, *hqk0, *hqk1, *hv0, *hv1, *ha0, *ha1, *hm0, *hm1, *hmid;
    __half *hwqk, *hwv, *hwo, *hwf1, *hwf2;
    cudaGetSymbolAddress((void**)&hx0,  g_hx0);
    cudaGetSymbolAddress((void**)&hx1,  g_hx1);
    cudaGetSymbolAddress((void**)&hqk0, g_hqk0);
    cudaGetSymbolAddress((void**)&hqk1, g_hqk1);
    cudaGetSymbolAddress((void**)&hv0,  g_hv0);
    cudaGetSymbolAddress((void**)&hv1,  g_hv1);
    cudaGetSymbolAddress((void**)&ha0,  g_ha0);
    cudaGetSymbolAddress((void**)&ha1,  g_ha1);
    cudaGetSymbolAddress((void**)&hm0,  g_hm0);
    cudaGetSymbolAddress((void**)&hm1,  g_hm1);
    cudaGetSymbolAddress((void**)&hmid, g_hmid);
    cudaGetSymbolAddress((void**)&hwqk, g_hwqk);
    cudaGetSymbolAddress((void**)&hwv,  g_hwv);
    cudaGetSymbolAddress((void**)&hwo,  g_hwo);
    cudaGetSymbolAddress((void**)&hwf1, g_hwf1);
    cudaGetSymbolAddress((void**)&hwf2, g_hwf2);

    cudaFuncSetAttribute(gemm_h<false,true>,  cudaFuncAttributeMaxDynamicSharedMemorySize, GSMEM);
    cudaFuncSetAttribute(gemm_h<false,false>, cudaFuncAttributeMaxDynamicSharedMemorySize, GSMEM);
    cudaFuncSetAttribute(gemm_h<true,true>,   cudaFuncAttributeMaxDynamicSharedMemorySize, GSMEM);
    cudaFuncSetAttribute(attn_h, cudaFuncAttributeMaxDynamicSharedMemorySize, ATTN_SMEM);

    // conversions
    const int NX = Mrows*Dmod, NW = Dmod*Dmod, NF1 = FFd*FFd, NF2 = Dmod*FFd;
    f2h_kernel<<<NX/1024, 256>>>(x0,  hx0,  NX);
    f2h_kernel<<<NX/1024, 256>>>(x1,  hx1,  NX);
    f2h_kernel<<<NW/1024, 256>>>(Wqk, hwqk, NW);
    f2h_kernel<<<NW/1024, 256>>>(Wv,  hwv,  NW);
    f2h_kernel<<<NW/1024, 256>>>(Wo,  hwo,  NW);
    f2h_kernel<<<NF1/1024, 256>>>(Wf1, hwf1, NF1);
    f2h_kernel<<<NF2/1024, 256>>>(Wf2, hwf2, NF2);

    dim3 g512(Dmod/128, Mrows/128);   // (4, 64)
    dim3 g1024(FFd/128, Mrows/128);   // (8, 64)
    dim3 ga(Bsz*Hh, Nseq/128);        // (32, 16)

    // projections -> fp16
    gemm_h<false,true><<<g512, 256, GSMEM>>>(hx0, nullptr, hwqk, bqk, nullptr, nullptr, hqk0, Mrows, Dmod, Dmod);
    gemm_h<false,true><<<g512, 256, GSMEM>>>(hx1, nullptr, hwqk, bqk, nullptr, nullptr, hqk1, Mrows, Dmod, Dmod);
    gemm_h<false,true><<<g512, 256, GSMEM>>>(hx0, nullptr, hwv,  bv,  nullptr, nullptr, hv0,  Mrows, Dmod, Dmod);
    gemm_h<false,true><<<g512, 256, GSMEM>>>(hx1, nullptr, hwv,  bv,  nullptr, nullptr, hv1,  Mrows, Dmod, Dmod);

    // cross attention (fp16 in/out)
    attn_h<<<ga, 256, ATTN_SMEM>>>(hqk0, hqk1, hv1, ha0);
    attn_h<<<ga, 256, ATTN_SMEM>>>(hqk1, hqk0, hv0, ha1);

    // output projection -> fp16
    gemm_h<false,true><<<g512, 256, GSMEM>>>(ha0, nullptr, hwo, bo, nullptr, nullptr, hm0, Mrows, Dmod, Dmod);
    gemm_h<false,true><<<g512, 256, GSMEM>>>(ha1, nullptr, hwo, bo, nullptr, nullptr, hm1, Mrows, Dmod, Dmod);

    // FFN stream 0 (concat fused into FFN1 A-loader)
    gemm_h<true,true><<<g1024, 256, GSMEM>>>(hx0, hm0, hwf1, bf1, nullptr, nullptr, hmid, Mrows, FFd, FFd);
    ln_gelu_h<<<Mrows, 256>>>(hmid, lng, lnb);
    gemm_h<false,false><<<g512, 256, GSMEM>>>(hmid, nullptr, hwf2, bf2, x0, out, nullptr, Mrows, Dmod, FFd);

    // FFN stream 1
    gemm_h<true,true><<<g1024, 256, GSMEM>>>(hx1, hm1, hwf1, bf1, nullptr, nullptr, hmid, Mrows, FFd, FFd);
    ln_gelu_h<<<Mrows, 256>>>(hmid, lng, lnb);
    gemm_h<false,false><<<g512, 256, GSMEM>>>(hmid, nullptr, hwf2, bf2, x1, out + (size_t)Mrows*Dmod, nullptr, Mrows, Dmod, FFd);
}

// round 13
// speedup vs baseline: 3.8008x; 1.2042x over previous
#include <cuda_runtime.h>
#include <cuda_fp16.h>
#include <math.h>
#include <stdint.h>

#define Bsz  4
#define Nseq 2048
#define Dmod 512
#define Hh   8
#define DHd  64
#define FFd  1024
#define Mrows (Bsz*Nseq)   // 8192

// ---------------- fp16 scratch ----------------
__device__ __half g_hx0  [Mrows*Dmod];
__device__ __half g_hx1  [Mrows*Dmod];
__device__ __half g_qkv0 [Mrows*FFd];   // [M][1024]: qk cols 0-511, v cols 512-1023
__device__ __half g_qkv1 [Mrows*FFd];
__device__ __half g_ha0  [Mrows*Dmod];
__device__ __half g_ha1  [Mrows*Dmod];
__device__ __half g_hm0  [Mrows*Dmod];
__device__ __half g_hm1  [Mrows*Dmod];
__device__ __half g_hmid0[Mrows*FFd];
__device__ __half g_hmid1[Mrows*FFd];
__device__ __half g_hwqk [Dmod*Dmod];
__device__ __half g_hwv  [Dmod*Dmod];
__device__ __half g_hwo  [Dmod*Dmod];
__device__ __half g_hwf1 [FFd*FFd];
__device__ __half g_hwf2 [Dmod*FFd];

// ---------------- helpers ----------------
__device__ __forceinline__ void mma_f16(float d[4], const uint32_t a[4], const uint32_t b[2]) {
    asm volatile(
        "mma.sync.aligned.m16n8k16.row.col.f32.f16.f16.f32 "
        "{%0,%1,%2,%3}, {%4,%5,%6,%7}, {%8,%9}, {%0,%1,%2,%3};\n"
        : "+f"(d[0]), "+f"(d[1]), "+f"(d[2]), "+f"(d[3])
        : "r"(a[0]), "r"(a[1]), "r"(a[2]), "r"(a[3]), "r"(b[0]), "r"(b[1]));
}
__device__ __forceinline__ void ldsm4(uint32_t r[4], uint32_t addr) {
    asm volatile("ldmatrix.sync.aligned.m8n8.x4.shared.b16 {%0,%1,%2,%3}, [%4];"
        : "=r"(r[0]), "=r"(r[1]), "=r"(r[2]), "=r"(r[3]) : "r"(addr));
}
__device__ __forceinline__ void ldsm4t(uint32_t r[4], uint32_t addr) {
    asm volatile("ldmatrix.sync.aligned.m8n8.x4.trans.shared.b16 {%0,%1,%2,%3}, [%4];"
        : "=r"(r[0]), "=r"(r[1]), "=r"(r[2]), "=r"(r[3]) : "r"(addr));
}
#define CP16(dst, src) asm volatile("cp.async.cg.shared.global [%0], [%1], 16;\n" :: "r"(dst), "l"(src))
#define CPCOMMIT()     asm volatile("cp.async.commit_group;\n" ::: "memory")
#define CPWAIT(n)      asm volatile("cp.async.wait_group %0;\n" :: "n"(n) : "memory")

// ---------------- f32 -> f16 conversion ----------------
__global__ void f2h_kernel(const float* __restrict__ s, __half* __restrict__ d, int n) {
    int i = (blockIdx.x * blockDim.x + threadIdx.x) * 4;
    if (i < n) {
        float4 v = *(const float4*)(s + i);
        __half2* dp = (__half2*)(d + i);
        dp[0] = __floats2half2_rn(v.x, v.y);
        dp[1] = __floats2half2_rn(v.z, v.w);
    }
}

// ---------------- FP16 GEMM: cp.async 3-stage + ldmatrix, m16n8k16, 2-stream ----------------
// Per z: C[M,N] = A[M,K]*W[N,K]^T + bias (+res when fp32 out).
// B split: output cols >= NS come from Wb/biasb (rows NS.. of the virtual weight).
// 128x128 tile, BK=64, 8 warps (2x4). smem: stage s: A @ s*32768, B @ +16384. (96 KB)
#define GSMEM 98304
template<bool CAT, bool OUTH>
__global__ __launch_bounds__(256, 2) void gemm_h(
    const __half* __restrict__ A0, const __half* __restrict__ A1,
    const __half* __restrict__ A20, const __half* __restrict__ A21,
    const __half* __restrict__ Wa, const __half* __restrict__ Wb,
    const float* __restrict__ biasa, const float* __restrict__ biasb,
    const float* __restrict__ res0, const float* __restrict__ res1,
    float* __restrict__ Cf0, float* __restrict__ Cf1,
    __half* __restrict__ Ch0, __half* __restrict__ Ch1,
    int N, int K, int NS)
{
    extern __shared__ float sm[];
    const uint32_t smB = (uint32_t)__cvta_generic_to_shared(sm);

    const int z = blockIdx.z;
    const __half* A   = z ? A1  : A0;
    const __half* A2  = z ? A21 : A20;
    const float*  res = z ? res1 : res0;
    float*  Cf = z ? Cf1 : Cf0;
    __half* Ch = z ? Ch1 : Ch0;

    const int tid  = threadIdx.x;
    const int wid  = tid >> 5, lane = tid & 31;
    const int g    = lane >> 2, tig = lane & 3;
    const int wm   = wid & 1,  wn   = wid >> 1;
    const int lr   = tid >> 3;
    const int lu   = tid & 7;
    const int j    = lane >> 3;
    const int jr   = (j & 1) * 8, jc = (j >> 1);
    const int l7   = lane & 7;

    const int arow0 = blockIdx.y * 128;
    const int brow0 = blockIdx.x * 128;

    // weight/bias half selection (each 128-col block lies entirely in one half)
    const __half* Wsel = (brow0 < NS) ? (Wa + (size_t)brow0 * K) : (Wb + (size_t)(brow0 - NS) * K);
    const float* biasSel = (brow0 < NS) ? biasa : biasb;
    const int coff = (brow0 < NS) ? 0 : NS;

    uint32_t rbA[4], rbB[2];
    #pragma unroll
    for (int m = 0; m < 4; m++) rbA[m] = (uint32_t)(wm*64 + m*16 + jr + l7) * 128u;
    #pragma unroll
    for (int np = 0; np < 2; np++) rbB[np] = (uint32_t)(wn*32 + np*16 + jr + l7) * 128u;

    const uint32_t cpOff = (uint32_t)(lr * 128 + ((lu ^ (lr & 7)) << 4));

    float acc[4][4][4];
    #pragma unroll
    for (int m = 0; m < 4; m++)
        #pragma unroll
        for (int n = 0; n < 4; n++)
            #pragma unroll
            for (int q = 0; q < 4; q++) acc[m][n][q] = 0.f;

    const int T = K / 64;

    auto issue = [&](int t, int s) {
        const int colg = t*64 + lu*8;
        const uint32_t dstA = smB + (uint32_t)s*32768u + cpOff;
        const uint32_t dstB = dstA + 16384u;
        #pragma unroll
        for (int i = 0; i < 4; i++) {
            int row = lr + 32*i;
            const __half* srcA;
            if (CAT) {
                srcA = (colg < 512) ? (A  + (size_t)(arow0+row)*512 + colg)
                                    : (A2 + (size_t)(arow0+row)*512 + colg - 512);
            } else {
                srcA = A + (size_t)(arow0+row)*K + colg;
            }
            CP16(dstA + i*4096u, srcA);
            CP16(dstB + i*4096u, Wsel + (size_t)row*K + colg);
        }
        CPCOMMIT();
    };

    issue(0, 0);
    issue(1, 1);
    int so = 0;

    for (int t = 0; t < T; t++) {
        if (t + 1 < T) { CPWAIT(1); } else { CPWAIT(0); }
        __syncthreads();
        if (t + 2 < T) {
            int s = so + 2;
            if (s >= 3) s -= 3;
            issue(t + 2, s);
        }

        const uint32_t aB = smB + (uint32_t)so * 32768u;
        const uint32_t bB = aB + 16384u;

        #pragma unroll
        for (int kk = 0; kk < 4; kk++) {
            const uint32_t xofs = (uint32_t)((((kk << 1) | jc) ^ l7) << 4);
            uint32_t af[4][4], bf[4][2];
            #pragma unroll
            for (int m = 0; m < 4; m++)
                ldsm4(af[m], aB + rbA[m] + xofs);
            #pragma unroll
            for (int np = 0; np < 2; np++) {
                uint32_t t4[4];
                ldsm4(t4, bB + rbB[np] + xofs);
                bf[2*np  ][0] = t4[0]; bf[2*np  ][1] = t4[2];
                bf[2*np+1][0] = t4[1]; bf[2*np+1][1] = t4[3];
            }
            #pragma unroll
            for (int m = 0; m < 4; m++)
                #pragma unroll
                for (int n = 0; n < 4; n++)
                    mma_f16(acc[m][n], af[m], bf[n]);
        }
        so = (so == 2) ? 0 : so + 1;
    }

    const int rb = arow0 + wm * 64;
    const int cb = brow0 + wn * 32;
    #pragma unroll
    for (int m = 0; m < 4; m++) {
        #pragma unroll
        for (int n = 0; n < 4; n++) {
            int row0 = rb + m*16 + g;
            int col  = cb + n*8 + tig*2;
            float b0 = biasSel[col - coff], b1 = biasSel[col - coff + 1];
            float v0 = acc[m][n][0] + b0, v1 = acc[m][n][1] + b1;
            float v2 = acc[m][n][2] + b0, v3 = acc[m][n][3] + b1;
            if (OUTH) {
                *(__half2*)(Ch + (size_t)row0     * N + col) = __floats2half2_rn(v0, v1);
                *(__half2*)(Ch + (size_t)(row0+8) * N + col) = __floats2half2_rn(v2, v3);
            } else {
                if (res) {
                    const float* r0p = res + (size_t)row0 * N + col;
                    const float* r1p = res + (size_t)(row0+8) * N + col;
                    v0 += r0p[0]; v1 += r0p[1];
                    v2 += r1p[0]; v3 += r1p[1];
                }
                *(float2*)(Cf + (size_t)row0     * N + col) = make_float2(v0, v1);
                *(float2*)(Cf + (size_t)(row0+8) * N + col) = make_float2(v2, v3);
            }
        }
    }
}

// ---------------- FP16 flash attention (2-direction via z) ----------------
// Reads fused qkv [b][n][1024] (qk cols 0-511, v cols 512-1023), writes O [b][n][512].
// z=0: Q=qkv0, K/V=qkv1 -> ha0 ; z=1: Q=qkv1, K/V=qkv0 -> ha1
#define KT 64
#define ATTN_SMEM 49152
#define LQ 1024

__global__ __launch_bounds__(256) void attn_h(
    const __half* __restrict__ qkv0, const __half* __restrict__ qkv1,
    __half* __restrict__ O0, __half* __restrict__ O1)
{
    extern __shared__ float smbuf[];
    const uint32_t smB = (uint32_t)__cvta_generic_to_shared(smbuf);
    char* smc = (char*)smbuf;

    const int z = blockIdx.z;
    const __half* Qb = z ? qkv1 : qkv0;
    const __half* Kb = z ? qkv0 : qkv1;
    __half* Ob = z ? O1 : O0;

    const int tid  = threadIdx.x;
    const int wid  = tid >> 5, lane = tid & 31;
    const int g    = lane >> 2, tig = lane & 3;
    const int j    = lane >> 3;
    const int jr   = (j & 1) * 8, jc = (j >> 1);
    const int l7   = lane & 7;

    const int bh = blockIdx.x;
    const int b  = bh >> 3, h = bh & 7;
    const size_t qbase = (size_t)b * (Nseq * LQ) + (size_t)h * DHd;
    const int qrow = blockIdx.y * 128 + wid * 16;

    uint32_t qf[4][4];
    {
        const __half* qp = Qb + qbase + (size_t)(qrow + g) * LQ;
        #pragma unroll
        for (int ks = 0; ks < 4; ks++) {
            qf[ks][0] = *(const uint32_t*)(qp + ks*16 + tig*2);
            qf[ks][1] = *(const uint32_t*)(qp + 8*LQ + ks*16 + tig*2);
            qf[ks][2] = *(const uint32_t*)(qp + ks*16 + 8 + tig*2);
            qf[ks][3] = *(const uint32_t*)(qp + 8*LQ + ks*16 + 8 + tig*2);
        }
    }

    float oacc[8][4];
    #pragma unroll
    for (int n = 0; n < 8; n++)
        #pragma unroll
        for (int q = 0; q < 4; q++) oacc[n][q] = 0.f;
    float m0 = -1e30f, m1 = -1e30f, l0 = 0.f, l1 = 0.f;

    const int lr = tid >> 3;
    const int lu = tid & 7;
    const __half* Kg = Kb + qbase + (size_t)lr * LQ + lu*8;
    const __half* Vg = Kg + 512;                      // v at col offset 512 in same rows
    const int pr = wid * 16 + g;

    const uint32_t kvOff = (uint32_t)(lr * 128 + ((lu ^ (lr & 7)) << 4));
    auto issueKV = [&](int kt) {
        const int s = kt & 1;
        const size_t off = (size_t)kt * KT * LQ;
        const uint32_t kd = smB + (uint32_t)s * 16384u + kvOff;
        const uint32_t vd = kd + 8192u;
        CP16(kd,          Kg + off);
        CP16(kd + 4096u,  Kg + off + 32*LQ);
        CP16(vd,          Vg + off);
        CP16(vd + 4096u,  Vg + off + 32*LQ);
        CPCOMMIT();
    };

    const uint32_t rbP = (uint32_t)(wid*16 + jr + l7) * 128u;

    issueKV(0);
    const int TKT = Nseq / KT;
    for (int kt = 0; kt < TKT; kt++) {
        if (kt + 1 < TKT) { issueKV(kt + 1); CPWAIT(1); } else { CPWAIT(0); }
        __syncthreads();

        const uint32_t Kst = smB + (uint32_t)(kt & 1) * 16384u;
        const uint32_t Vst = Kst + 8192u;

        float sacc[8][4];
        #pragma unroll
        for (int n = 0; n < 8; n++)
            #pragma unroll
            for (int q = 0; q < 4; q++) sacc[n][q] = 0.f;

        #pragma unroll
        for (int kk = 0; kk < 4; kk++) {
            const uint32_t xofs = (uint32_t)((((kk << 1) | jc) ^ l7) << 4);
            uint32_t bf[8][2];
            #pragma unroll
            for (int p = 0; p < 4; p++) {
                uint32_t t4[4];
                ldsm4(t4, Kst + (uint32_t)((p*16 + jr + l7) * 128) + xofs);
                bf[2*p  ][0] = t4[0]; bf[2*p  ][1] = t4[2];
                bf[2*p+1][0] = t4[1]; bf[2*p+1][1] = t4[3];
            }
            #pragma unroll
            for (int n = 0; n < 8; n++) mma_f16(sacc[n], qf[kk], bf[n]);
        }

        float t0 = -1e30f, t1 = -1e30f;
        #pragma unroll
        for (int n = 0; n < 8; n++) {
            sacc[n][0] *= 0.125f; sacc[n][1] *= 0.125f;
            sacc[n][2] *= 0.125f; sacc[n][3] *= 0.125f;
            t0 = fmaxf(t0, fmaxf(sacc[n][0], sacc[n][1]));
            t1 = fmaxf(t1, fmaxf(sacc[n][2], sacc[n][3]));
        }
        t0 = fmaxf(t0, __shfl_xor_sync(0xffffffffu, t0, 1));
        t0 = fmaxf(t0, __shfl_xor_sync(0xffffffffu, t0, 2));
        t1 = fmaxf(t1, __shfl_xor_sync(0xffffffffu, t1, 1));
        t1 = fmaxf(t1, __shfl_xor_sync(0xffffffffu, t1, 2));

        float mn0 = fmaxf(m0, t0), mn1 = fmaxf(m1, t1);
        float c0 = __expf(m0 - mn0), c1 = __expf(m1 - mn1);
        m0 = mn0; m1 = mn1;

        float ps0 = 0.f, ps1 = 0.f;
        #pragma unroll
        for (int n = 0; n < 8; n++) {
            float p00 = __expf(sacc[n][0] - m0), p01 = __expf(sacc[n][1] - m0);
            float p10 = __expf(sacc[n][2] - m1), p11 = __expf(sacc[n][3] - m1);
            ps0 += p00 + p01; ps1 += p10 + p11;
            sacc[n][0] = p00; sacc[n][1] = p01; sacc[n][2] = p10; sacc[n][3] = p11;
        }
        ps0 += __shfl_xor_sync(0xffffffffu, ps0, 1);
        ps0 += __shfl_xor_sync(0xffffffffu, ps0, 2);
        ps1 += __shfl_xor_sync(0xffffffffu, ps1, 1);
        ps1 += __shfl_xor_sync(0xffffffffu, ps1, 2);
        l0 = l0 * c0 + ps0;
        l1 = l1 * c1 + ps1;
        #pragma unroll
        for (int n = 0; n < 8; n++) {
            oacc[n][0] *= c0; oacc[n][1] *= c0;
            oacc[n][2] *= c1; oacc[n][3] *= c1;
        }

        #pragma unroll
        for (int n = 0; n < 8; n++) {
            uint32_t po = 32768u + (uint32_t)(pr * 128) + (uint32_t)(((n ^ g) << 4) + tig*4);
            *(__half2*)(smc + po)        = __floats2half2_rn(sacc[n][0], sacc[n][1]);
            *(__half2*)(smc + po + 1024) = __floats2half2_rn(sacc[n][2], sacc[n][3]);
        }
        __syncwarp();

        #pragma unroll
        for (int ks = 0; ks < 4; ks++) {
            uint32_t af[4];
            ldsm4(af, smB + 32768u + rbP + (uint32_t)((((ks << 1) | jc) ^ l7) << 4));
            const uint32_t vrow = (uint32_t)((ks*16 + jr + l7) * 128);
            #pragma unroll
            for (int p = 0; p < 4; p++) {
                uint32_t t4[4];
                ldsm4t(t4, Vst + vrow + (uint32_t)((((p << 1) | jc) ^ l7) << 4));
                uint32_t bv0[2] = { t4[0], t4[1] };
                uint32_t bv1[2] = { t4[2], t4[3] };
                mma_f16(oacc[2*p  ], af, bv0);
                mma_f16(oacc[2*p+1], af, bv1);
            }
        }
        __syncthreads();
    }

    float i0 = 1.f / l0, i1 = 1.f / l1;
    __half* Op = Ob + (size_t)b * (Nseq * Dmod) + (size_t)h * DHd + (size_t)(qrow + g) * Dmod;
    #pragma unroll
    for (int n = 0; n < 8; n++) {
        *(__half2*)(Op + n*8 + tig*2)          = __floats2half2_rn(oacc[n][0]*i0, oacc[n][1]*i0);
        *(__half2*)(Op + 8*Dmod + n*8 + tig*2) = __floats2half2_rn(oacc[n][2]*i1, oacc[n][3]*i1);
    }
}

// ---------------- LayerNorm(1024) + exact GELU, fp16, 2-stream ----------------
__global__ __launch_bounds__(256) void ln_gelu_h(
    __half* __restrict__ Hm0, __half* __restrict__ Hm1,
    const float* __restrict__ gw, const float* __restrict__ bw)
{
    __shared__ float red1[8];
    __shared__ float red2[8];
    __shared__ float s_mu, s_inv;

    const int row = blockIdx.x;
    const int tid = threadIdx.x;
    __half* hp = (blockIdx.y ? Hm1 : Hm0) + (size_t)row * FFd;

    float v[4];
    float s = 0.f;
    #pragma unroll
    for (int i = 0; i < 4; i++) { v[i] = __half2float(hp[tid + i*256]); s += v[i]; }

    #pragma unroll
    for (int off = 16; off; off >>= 1) s += __shfl_xor_sync(0xffffffffu, s, off);
    if ((tid & 31) == 0) red1[tid >> 5] = s;
    __syncthreads();
    if (tid == 0) {
        float t = 0.f;
        #pragma unroll
        for (int w = 0; w < 8; w++) t += red1[w];
        s_mu = t * (1.f / FFd);
    }
    __syncthreads();
    const float mu = s_mu;

    float ss = 0.f;
    #pragma unroll
    for (int i = 0; i < 4; i++) { float d = v[i] - mu; ss += d*d; }
    #pragma unroll
    for (int off = 16; off; off >>= 1) ss += __shfl_xor_sync(0xffffffffu, ss, off);
    if ((tid & 31) == 0) red2[tid >> 5] = ss;
    __syncthreads();
    if (tid == 0) {
        float t = 0.f;
        #pragma unroll
        for (int w = 0; w < 8; w++) t += red2[w];
        s_inv = rsqrtf(t * (1.f / FFd) + 1e-5f);
    }
    __syncthreads();
    const float inv = s_inv;

    #pragma unroll
    for (int i = 0; i < 4; i++) {
        int c = tid + i*256;
        float x = (v[i] - mu) * inv * gw[c] + bw[c];
        hp[c] = __float2half_rn(0.5f * x * (1.f + erff(x * 0.70710678118654752f)));
    }
}

// ---------------- launcher ----------------
extern "C" void kernel_launch(void* const* d_in, const int* in_sizes, int n_in,
                              void* d_out, int out_size)
{
    const float* x0  = (const float*)d_in[0];
    const float* x1  = (const float*)d_in[1];
    const float* Wqk = (const float*)d_in[2];
    const float* bqk = (const float*)d_in[3];
    const float* Wv  = (const float*)d_in[4];
    const float* bv  = (const float*)d_in[5];
    const float* Wo  = (const float*)d_in[6];
    const float* bo  = (const float*)d_in[7];
    const float* Wf1 = (const float*)d_in[8];
    const float* bf1 = (const float*)d_in[9];
    const float* lng = (const float*)d_in[10];
    const float* lnb = (const float*)d_in[11];
    const float* Wf2 = (const float*)d_in[12];
    const float* bf2 = (const float*)d_in[13];
    float* out = (float*)d_out;

    __half *hx0, *hx1, *qkv0, *qkv1, *ha0, *ha1, *hm0, *hm1, *hmid0, *hmid1;
    __half *hwqk, *hwv, *hwo, *hwf1, *hwf2;
    cudaGetSymbolAddress((void**)&hx0,   g_hx0);
    cudaGetSymbolAddress((void**)&hx1,   g_hx1);
    cudaGetSymbolAddress((void**)&qkv0,  g_qkv0);
    cudaGetSymbolAddress((void**)&qkv1,  g_qkv1);
    cudaGetSymbolAddress((void**)&ha0,   g_ha0);
    cudaGetSymbolAddress((void**)&ha1,   g_ha1);
    cudaGetSymbolAddress((void**)&hm0,   g_hm0);
    cudaGetSymbolAddress((void**)&hm1,   g_hm1);
    cudaGetSymbolAddress((void**)&hmid0, g_hmid0);
    cudaGetSymbolAddress((void**)&hmid1, g_hmid1);
    cudaGetSymbolAddress((void**)&hwqk,  g_hwqk);
    cudaGetSymbolAddress((void**)&hwv,   g_hwv);
    cudaGetSymbolAddress((void**)&hwo,   g_hwo);
    cudaGetSymbolAddress((void**)&hwf1,  g_hwf1);
    cudaGetSymbolAddress((void**)&hwf2,  g_hwf2);

    cudaFuncSetAttribute(gemm_h<false,true>,  cudaFuncAttributeMaxDynamicSharedMemorySize, GSMEM);
    cudaFuncSetAttribute(gemm_h<false,false>, cudaFuncAttributeMaxDynamicSharedMemorySize, GSMEM);
    cudaFuncSetAttribute(gemm_h<true,true>,   cudaFuncAttributeMaxDynamicSharedMemorySize, GSMEM);
    cudaFuncSetAttribute(attn_h, cudaFuncAttributeMaxDynamicSharedMemorySize, ATTN_SMEM);

    // conversions
    const int NX = Mrows*Dmod, NW = Dmod*Dmod, NF1 = FFd*FFd, NF2 = Dmod*FFd;
    f2h_kernel<<<NX/1024, 256>>>(x0,  hx0,  NX);
    f2h_kernel<<<NX/1024, 256>>>(x1,  hx1,  NX);
    f2h_kernel<<<NW/1024, 256>>>(Wqk, hwqk, NW);
    f2h_kernel<<<NW/1024, 256>>>(Wv,  hwv,  NW);
    f2h_kernel<<<NW/1024, 256>>>(Wo,  hwo,  NW);
    f2h_kernel<<<NF1/1024, 256>>>(Wf1, hwf1, NF1);
    f2h_kernel<<<NF2/1024, 256>>>(Wf2, hwf2, NF2);

    const int BIG = 1 << 28;
    dim3 gproj(FFd/128, Mrows/128, 2);   // (8, 64, 2) N=1024
    dim3 g512z(Dmod/128, Mrows/128, 2);  // (4, 64, 2)
    dim3 g1024z(FFd/128, Mrows/128, 2);  // (8, 64, 2)
    dim3 ga(Bsz*Hh, Nseq/128, 2);        // (32, 16, 2)
    dim3 gln(Mrows, 2);

    // fused QK+V projection -> qkv [M][1024]
    gemm_h<false,true><<<gproj, 256, GSMEM>>>(
        hx0, hx1, nullptr, nullptr, hwqk, hwv, bqk, bv,
        nullptr, nullptr, nullptr, nullptr, qkv0, qkv1, FFd, Dmod, Dmod);

    // cross attention (both directions)
    attn_h<<<ga, 256, ATTN_SMEM>>>(qkv0, qkv1, ha0, ha1);

    // output projection -> hm
    gemm_h<false,true><<<g512z, 256, GSMEM>>>(
        ha0, ha1, nullptr, nullptr, hwo, hwo, bo, bo,
        nullptr, nullptr, nullptr, nullptr, hm0, hm1, Dmod, Dmod, BIG);

    // FFN1 (concat fused) -> hmid
    gemm_h<true,true><<<g1024z, 256, GSMEM>>>(
        hx0, hx1, hm0, hm1, hwf1, hwf1, bf1, bf1,
        nullptr, nullptr, nullptr, nullptr, hmid0, hmid1, FFd, FFd, BIG);

    // LayerNorm + GELU
    ln_gelu_h<<<gln, 256>>>(hmid0, hmid1, lng, lnb);

    // FFN2 + residual -> out (fp32)
    gemm_h<false,false><<<g512z, 256, GSMEM>>>(
        hmid0, hmid1, nullptr, nullptr, hwf2, hwf2, bf2, bf2,
        x0, x1, out, out + (size_t)Mrows*Dmod, nullptr, nullptr, Dmod, FFd, BIG);
}

// round 14
// speedup vs baseline: 4.1723x; 1.0977x over previous
#include <cuda_runtime.h>
#include <cuda_fp16.h>
#include <math.h>
#include <stdint.h>

#define Bsz  4
#define Nseq 2048
#define Dmod 512
#define Hh   8
#define DHd  64
#define FFd  1024
#define Mrows (Bsz*Nseq)   // 8192

// ---------------- fp16 scratch ----------------
__device__ __half g_hx0  [Mrows*Dmod];
__device__ __half g_hx1  [Mrows*Dmod];
__device__ __half g_qkv0 [Mrows*FFd];   // [M][1024]: qk cols 0-511, v cols 512-1023
__device__ __half g_qkv1 [Mrows*FFd];
__device__ __half g_ha0  [Mrows*Dmod];
__device__ __half g_ha1  [Mrows*Dmod];
__device__ __half g_hm0  [Mrows*Dmod];
__device__ __half g_hm1  [Mrows*Dmod];
__device__ __half g_hmid0[Mrows*FFd];
__device__ __half g_hmid1[Mrows*FFd];
__device__ __half g_hwqk [Dmod*Dmod];
__device__ __half g_hwv  [Dmod*Dmod];
__device__ __half g_hwo  [Dmod*Dmod];
__device__ __half g_hwf1 [FFd*FFd];
__device__ __half g_hwf2 [Dmod*FFd];

// ---------------- helpers ----------------
__device__ __forceinline__ void mma_f16(float d[4], const uint32_t a[4], const uint32_t b[2]) {
    asm volatile(
        "mma.sync.aligned.m16n8k16.row.col.f32.f16.f16.f32 "
        "{%0,%1,%2,%3}, {%4,%5,%6,%7}, {%8,%9}, {%0,%1,%2,%3};\n"
        : "+f"(d[0]), "+f"(d[1]), "+f"(d[2]), "+f"(d[3])
        : "r"(a[0]), "r"(a[1]), "r"(a[2]), "r"(a[3]), "r"(b[0]), "r"(b[1]));
}
__device__ __forceinline__ void ldsm4(uint32_t r[4], uint32_t addr) {
    asm volatile("ldmatrix.sync.aligned.m8n8.x4.shared.b16 {%0,%1,%2,%3}, [%4];"
        : "=r"(r[0]), "=r"(r[1]), "=r"(r[2]), "=r"(r[3]) : "r"(addr));
}
__device__ __forceinline__ void ldsm4t(uint32_t r[4], uint32_t addr) {
    asm volatile("ldmatrix.sync.aligned.m8n8.x4.trans.shared.b16 {%0,%1,%2,%3}, [%4];"
        : "=r"(r[0]), "=r"(r[1]), "=r"(r[2]), "=r"(r[3]) : "r"(addr));
}
__device__ __forceinline__ uint32_t packh2(float a, float b) {
    __half2 h = __floats2half2_rn(a, b);
    return *(uint32_t*)&h;
}
#define CP16(dst, src) asm volatile("cp.async.cg.shared.global [%0], [%1], 16;\n" :: "r"(dst), "l"(src))
#define CPCOMMIT()     asm volatile("cp.async.commit_group;\n" ::: "memory")
#define CPWAIT(n)      asm volatile("cp.async.wait_group %0;\n" :: "n"(n) : "memory")

// ---------------- fused f32 -> f16 conversion (all 7 tensors, one launch) ----------------
// element ranges (all multiples of 4): x0 x1 wqk wv wo wf1 wf2
#define R_X0  0L
#define R_X1  4194304L
#define R_WQK 8388608L
#define R_WV  8650752L
#define R_WO  8912896L
#define R_WF1 9175040L
#define R_WF2 10223616L
#define R_END 10747904L
__global__ void f2h_all(
    const float* __restrict__ x0,  const float* __restrict__ x1,
    const float* __restrict__ wqk, const float* __restrict__ wv,
    const float* __restrict__ wo,  const float* __restrict__ wf1,
    const float* __restrict__ wf2,
    __half* __restrict__ hx0, __half* __restrict__ hx1,
    __half* __restrict__ hwqk, __half* __restrict__ hwv,
    __half* __restrict__ hwo, __half* __restrict__ hwf1, __half* __restrict__ hwf2)
{
    long idx = ((long)blockIdx.x * blockDim.x + threadIdx.x) * 4;
    if (idx >= R_END) return;
    const float* s; __half* d; long off;
    if      (idx < R_X1)  { s = x0;  d = hx0;  off = R_X0;  }
    else if (idx < R_WQK) { s = x1;  d = hx1;  off = R_X1;  }
    else if (idx < R_WV)  { s = wqk; d = hwqk; off = R_WQK; }
    else if (idx < R_WO)  { s = wv;  d = hwv;  off = R_WV;  }
    else if (idx < R_WF1) { s = wo;  d = hwo;  off = R_WO;  }
    else if (idx < R_WF2) { s = wf1; d = hwf1; off = R_WF1; }
    else                  { s = wf2; d = hwf2; off = R_WF2; }
    long i = idx - off;
    float4 v = *(const float4*)(s + i);
    __half2* dp = (__half2*)(d + i);
    dp[0] = __floats2half2_rn(v.x, v.y);
    dp[1] = __floats2half2_rn(v.z, v.w);
}

// ---------------- FP16 GEMM: cp.async 3-stage + ldmatrix, m16n8k16, 2-stream ----------------
#define GSMEM 98304
template<bool CAT, bool OUTH>
__global__ __launch_bounds__(256, 2) void gemm_h(
    const __half* __restrict__ A0, const __half* __restrict__ A1,
    const __half* __restrict__ A20, const __half* __restrict__ A21,
    const __half* __restrict__ Wa, const __half* __restrict__ Wb,
    const float* __restrict__ biasa, const float* __restrict__ biasb,
    const float* __restrict__ res0, const float* __restrict__ res1,
    float* __restrict__ Cf0, float* __restrict__ Cf1,
    __half* __restrict__ Ch0, __half* __restrict__ Ch1,
    int N, int K, int NS)
{
    extern __shared__ float sm[];
    const uint32_t smB = (uint32_t)__cvta_generic_to_shared(sm);

    const int z = blockIdx.z;
    const __half* A   = z ? A1  : A0;
    const __half* A2  = z ? A21 : A20;
    const float*  res = z ? res1 : res0;
    float*  Cf = z ? Cf1 : Cf0;
    __half* Ch = z ? Ch1 : Ch0;

    const int tid  = threadIdx.x;
    const int wid  = tid >> 5, lane = tid & 31;
    const int g    = lane >> 2, tig = lane & 3;
    const int wm   = wid & 1,  wn   = wid >> 1;
    const int lr   = tid >> 3;
    const int lu   = tid & 7;
    const int j    = lane >> 3;
    const int jr   = (j & 1) * 8, jc = (j >> 1);
    const int l7   = lane & 7;

    const int arow0 = blockIdx.y * 128;
    const int brow0 = blockIdx.x * 128;

    const __half* Wsel = (brow0 < NS) ? (Wa + (size_t)brow0 * K) : (Wb + (size_t)(brow0 - NS) * K);
    const float* biasSel = (brow0 < NS) ? biasa : biasb;
    const int coff = (brow0 < NS) ? 0 : NS;

    uint32_t rbA[4], rbB[2];
    #pragma unroll
    for (int m = 0; m < 4; m++) rbA[m] = (uint32_t)(wm*64 + m*16 + jr + l7) * 128u;
    #pragma unroll
    for (int np = 0; np < 2; np++) rbB[np] = (uint32_t)(wn*32 + np*16 + jr + l7) * 128u;

    const uint32_t cpOff = (uint32_t)(lr * 128 + ((lu ^ (lr & 7)) << 4));

    float acc[4][4][4];
    #pragma unroll
    for (int m = 0; m < 4; m++)
        #pragma unroll
        for (int n = 0; n < 4; n++)
            #pragma unroll
            for (int q = 0; q < 4; q++) acc[m][n][q] = 0.f;

    const int T = K / 64;

    auto issue = [&](int t, int s) {
        const int colg = t*64 + lu*8;
        const uint32_t dstA = smB + (uint32_t)s*32768u + cpOff;
        const uint32_t dstB = dstA + 16384u;
        #pragma unroll
        for (int i = 0; i < 4; i++) {
            int row = lr + 32*i;
            const __half* srcA;
            if (CAT) {
                srcA = (colg < 512) ? (A  + (size_t)(arow0+row)*512 + colg)
                                    : (A2 + (size_t)(arow0+row)*512 + colg - 512);
            } else {
                srcA = A + (size_t)(arow0+row)*K + colg;
            }
            CP16(dstA + i*4096u, srcA);
            CP16(dstB + i*4096u, Wsel + (size_t)row*K + colg);
        }
        CPCOMMIT();
    };

    issue(0, 0);
    issue(1, 1);
    int so = 0;

    for (int t = 0; t < T; t++) {
        if (t + 1 < T) { CPWAIT(1); } else { CPWAIT(0); }
        __syncthreads();
        if (t + 2 < T) {
            int s = so + 2;
            if (s >= 3) s -= 3;
            issue(t + 2, s);
        }

        const uint32_t aB = smB + (uint32_t)so * 32768u;
        const uint32_t bB = aB + 16384u;

        #pragma unroll
        for (int kk = 0; kk < 4; kk++) {
            const uint32_t xofs = (uint32_t)((((kk << 1) | jc) ^ l7) << 4);
            uint32_t af[4][4], bf[4][2];
            #pragma unroll
            for (int m = 0; m < 4; m++)
                ldsm4(af[m], aB + rbA[m] + xofs);
            #pragma unroll
            for (int np = 0; np < 2; np++) {
                uint32_t t4[4];
                ldsm4(t4, bB + rbB[np] + xofs);
                bf[2*np  ][0] = t4[0]; bf[2*np  ][1] = t4[2];
                bf[2*np+1][0] = t4[1]; bf[2*np+1][1] = t4[3];
            }
            #pragma unroll
            for (int m = 0; m < 4; m++)
                #pragma unroll
                for (int n = 0; n < 4; n++)
                    mma_f16(acc[m][n], af[m], bf[n]);
        }
        so = (so == 2) ? 0 : so + 1;
    }

    const int rb = arow0 + wm * 64;
    const int cb = brow0 + wn * 32;
    #pragma unroll
    for (int m = 0; m < 4; m++) {
        #pragma unroll
        for (int n = 0; n < 4; n++) {
            int row0 = rb + m*16 + g;
            int col  = cb + n*8 + tig*2;
            float b0 = biasSel[col - coff], b1 = biasSel[col - coff + 1];
            float v0 = acc[m][n][0] + b0, v1 = acc[m][n][1] + b1;
            float v2 = acc[m][n][2] + b0, v3 = acc[m][n][3] + b1;
            if (OUTH) {
                *(__half2*)(Ch + (size_t)row0     * N + col) = __floats2half2_rn(v0, v1);
                *(__half2*)(Ch + (size_t)(row0+8) * N + col) = __floats2half2_rn(v2, v3);
            } else {
                if (res) {
                    const float* r0p = res + (size_t)row0 * N + col;
                    const float* r1p = res + (size_t)(row0+8) * N + col;
                    v0 += r0p[0]; v1 += r0p[1];
                    v2 += r1p[0]; v3 += r1p[1];
                }
                *(float2*)(Cf + (size_t)row0     * N + col) = make_float2(v0, v1);
                *(float2*)(Cf + (size_t)(row0+8) * N + col) = make_float2(v2, v3);
            }
        }
    }
}

// ---------------- FP16 flash attention (2-direction via z), P kept in registers ----------------
// smem bytes: stage s: K @ s*16384, V @ s*16384+8192.  (32 KB)
#define KT 64
#define ATTN_SMEM 32768
#define LQ 1024

__global__ __launch_bounds__(256) void attn_h(
    const __half* __restrict__ qkv0, const __half* __restrict__ qkv1,
    __half* __restrict__ O0, __half* __restrict__ O1)
{
    extern __shared__ float smbuf[];
    const uint32_t smB = (uint32_t)__cvta_generic_to_shared(smbuf);

    const int z = blockIdx.z;
    const __half* Qb = z ? qkv1 : qkv0;
    const __half* Kb = z ? qkv0 : qkv1;
    __half* Ob = z ? O1 : O0;

    const int tid  = threadIdx.x;
    const int wid  = tid >> 5, lane = tid & 31;
    const int g    = lane >> 2, tig = lane & 3;
    const int j    = lane >> 3;
    const int jr   = (j & 1) * 8, jc = (j >> 1);
    const int l7   = lane & 7;

    const int bh = blockIdx.x;
    const int b  = bh >> 3, h = bh & 7;
    const size_t qbase = (size_t)b * (Nseq * LQ) + (size_t)h * DHd;
    const int qrow = blockIdx.y * 128 + wid * 16;

    // Q fragments, pre-scaled by 1/8 (exact in fp16)
    uint32_t qf[4][4];
    {
        const __half* qp = Qb + qbase + (size_t)(qrow + g) * LQ;
        const __half2 sc = __float2half2_rn(0.125f);
        #pragma unroll
        for (int ks = 0; ks < 4; ks++) {
            __half2 q0 = *(const __half2*)(qp + ks*16 + tig*2);
            __half2 q1 = *(const __half2*)(qp + 8*LQ + ks*16 + tig*2);
            __half2 q2 = *(const __half2*)(qp + ks*16 + 8 + tig*2);
            __half2 q3 = *(const __half2*)(qp + 8*LQ + ks*16 + 8 + tig*2);
            q0 = __hmul2(q0, sc); q1 = __hmul2(q1, sc);
            q2 = __hmul2(q2, sc); q3 = __hmul2(q3, sc);
            qf[ks][0] = *(uint32_t*)&q0; qf[ks][1] = *(uint32_t*)&q1;
            qf[ks][2] = *(uint32_t*)&q2; qf[ks][3] = *(uint32_t*)&q3;
        }
    }

    float oacc[8][4];
    #pragma unroll
    for (int n = 0; n < 8; n++)
        #pragma unroll
        for (int q = 0; q < 4; q++) oacc[n][q] = 0.f;
    float m0 = -1e30f, m1 = -1e30f, l0 = 0.f, l1 = 0.f;

    const int lr = tid >> 3;
    const int lu = tid & 7;
    const __half* Kg = Kb + qbase + (size_t)lr * LQ + lu*8;
    const __half* Vg = Kg + 512;

    const uint32_t kvOff = (uint32_t)(lr * 128 + ((lu ^ (lr & 7)) << 4));
    auto issueKV = [&](int kt) {
        const int s = kt & 1;
        const size_t off = (size_t)kt * KT * LQ;
        const uint32_t kd = smB + (uint32_t)s * 16384u + kvOff;
        const uint32_t vd = kd + 8192u;
        CP16(kd,          Kg + off);
        CP16(kd + 4096u,  Kg + off + 32*LQ);
        CP16(vd,          Vg + off);
        CP16(vd + 4096u,  Vg + off + 32*LQ);
        CPCOMMIT();
    };

    issueKV(0);
    const int TKT = Nseq / KT;
    for (int kt = 0; kt < TKT; kt++) {
        if (kt + 1 < TKT) { issueKV(kt + 1); CPWAIT(1); } else { CPWAIT(0); }
        __syncthreads();

        const uint32_t Kst = smB + (uint32_t)(kt & 1) * 16384u;
        const uint32_t Vst = Kst + 8192u;

        float sacc[8][4];
        #pragma unroll
        for (int n = 0; n < 8; n++)
            #pragma unroll
            for (int q = 0; q < 4; q++) sacc[n][q] = 0.f;

        #pragma unroll
        for (int kk = 0; kk < 4; kk++) {
            const uint32_t xofs = (uint32_t)((((kk << 1) | jc) ^ l7) << 4);
            uint32_t bf[8][2];
            #pragma unroll
            for (int p = 0; p < 4; p++) {
                uint32_t t4[4];
                ldsm4(t4, Kst + (uint32_t)((p*16 + jr + l7) * 128) + xofs);
                bf[2*p  ][0] = t4[0]; bf[2*p  ][1] = t4[2];
                bf[2*p+1][0] = t4[1]; bf[2*p+1][1] = t4[3];
            }
            #pragma unroll
            for (int n = 0; n < 8; n++) mma_f16(sacc[n], qf[kk], bf[n]);
        }

        // online softmax (scores already scaled via Q)
        float t0 = -1e30f, t1 = -1e30f;
        #pragma unroll
        for (int n = 0; n < 8; n++) {
            t0 = fmaxf(t0, fmaxf(sacc[n][0], sacc[n][1]));
            t1 = fmaxf(t1, fmaxf(sacc[n][2], sacc[n][3]));
        }
        t0 = fmaxf(t0, __shfl_xor_sync(0xffffffffu, t0, 1));
        t0 = fmaxf(t0, __shfl_xor_sync(0xffffffffu, t0, 2));
        t1 = fmaxf(t1, __shfl_xor_sync(0xffffffffu, t1, 1));
        t1 = fmaxf(t1, __shfl_xor_sync(0xffffffffu, t1, 2));

        float mn0 = fmaxf(m0, t0), mn1 = fmaxf(m1, t1);
        float c0 = __expf(m0 - mn0), c1 = __expf(m1 - mn1);
        m0 = mn0; m1 = mn1;

        float ps0 = 0.f, ps1 = 0.f;
        #pragma unroll
        for (int n = 0; n < 8; n++) {
            float p00 = __expf(sacc[n][0] - m0), p01 = __expf(sacc[n][1] - m0);
            float p10 = __expf(sacc[n][2] - m1), p11 = __expf(sacc[n][3] - m1);
            ps0 += p00 + p01; ps1 += p10 + p11;
            sacc[n][0] = p00; sacc[n][1] = p01; sacc[n][2] = p10; sacc[n][3] = p11;
        }
        ps0 += __shfl_xor_sync(0xffffffffu, ps0, 1);
        ps0 += __shfl_xor_sync(0xffffffffu, ps0, 2);
        ps1 += __shfl_xor_sync(0xffffffffu, ps1, 1);
        ps1 += __shfl_xor_sync(0xffffffffu, ps1, 2);
        l0 = l0 * c0 + ps0;
        l1 = l1 * c1 + ps1;
        #pragma unroll
        for (int n = 0; n < 8; n++) {
            oacc[n][0] *= c0; oacc[n][1] *= c0;
            oacc[n][2] *= c1; oacc[n][3] *= c1;
        }

        // O += P V : P fragment built directly in registers (C-frag == A-frag layout),
        // V via ldsm.trans (B), V smem [key][dh]
        #pragma unroll
        for (int ks = 0; ks < 4; ks++) {
            uint32_t af[4];
            af[0] = packh2(sacc[2*ks  ][0], sacc[2*ks  ][1]);   // row g,   k lo
            af[1] = packh2(sacc[2*ks  ][2], sacc[2*ks  ][3]);   // row g+8, k lo
            af[2] = packh2(sacc[2*ks+1][0], sacc[2*ks+1][1]);   // row g,   k hi
            af[3] = packh2(sacc[2*ks+1][2], sacc[2*ks+1][3]);   // row g+8, k hi
            const uint32_t vrow = (uint32_t)((ks*16 + jr + l7) * 128);
            #pragma unroll
            for (int p = 0; p < 4; p++) {
                uint32_t t4[4];
                ldsm4t(t4, Vst + vrow + (uint32_t)((((p << 1) | jc) ^ l7) << 4));
                uint32_t bv0[2] = { t4[0], t4[1] };
                uint32_t bv1[2] = { t4[2], t4[3] };
                mma_f16(oacc[2*p  ], af, bv0);
                mma_f16(oacc[2*p+1], af, bv1);
            }
        }
        __syncthreads();
    }

    float i0 = 1.f / l0, i1 = 1.f / l1;
    __half* Op = Ob + (size_t)b * (Nseq * Dmod) + (size_t)h * DHd + (size_t)(qrow + g) * Dmod;
    #pragma unroll
    for (int n = 0; n < 8; n++) {
        *(__half2*)(Op + n*8 + tig*2)          = __floats2half2_rn(oacc[n][0]*i0, oacc[n][1]*i0);
        *(__half2*)(Op + 8*Dmod + n*8 + tig*2) = __floats2half2_rn(oacc[n][2]*i1, oacc[n][3]*i1);
    }
}

// ---------------- LayerNorm(1024) + exact GELU, fp16, 2-stream ----------------
__global__ __launch_bounds__(256) void ln_gelu_h(
    __half* __restrict__ Hm0, __half* __restrict__ Hm1,
    const float* __restrict__ gw, const float* __restrict__ bw)
{
    __shared__ float red1[8];
    __shared__ float red2[8];
    __shared__ float s_mu, s_inv;

    const int row = blockIdx.x;
    const int tid = threadIdx.x;
    __half* hp = (blockIdx.y ? Hm1 : Hm0) + (size_t)row * FFd;

    float v[4];
    float s = 0.f;
    #pragma unroll
    for (int i = 0; i < 4; i++) { v[i] = __half2float(hp[tid + i*256]); s += v[i]; }

    #pragma unroll
    for (int off = 16; off; off >>= 1) s += __shfl_xor_sync(0xffffffffu, s, off);
    if ((tid & 31) == 0) red1[tid >> 5] = s;
    __syncthreads();
    if (tid == 0) {
        float t = 0.f;
        #pragma unroll
        for (int w = 0; w < 8; w++) t += red1[w];
        s_mu = t * (1.f / FFd);
    }
    __syncthreads();
    const float mu = s_mu;

    float ss = 0.f;
    #pragma unroll
    for (int i = 0; i < 4; i++) { float d = v[i] - mu; ss += d*d; }
    #pragma unroll
    for (int off = 16; off; off >>= 1) ss += __shfl_xor_sync(0xffffffffu, ss, off);
    if ((tid & 31) == 0) red2[tid >> 5] = ss;
    __syncthreads();
    if (tid == 0) {
        float t = 0.f;
        #pragma unroll
        for (int w = 0; w < 8; w++) t += red2[w];
        s_inv = rsqrtf(t * (1.f / FFd) + 1e-5f);
    }
    __syncthreads();
    const float inv = s_inv;

    #pragma unroll
    for (int i = 0; i < 4; i++) {
        int c = tid + i*256;
        float x = (v[i] - mu) * inv * gw[c] + bw[c];
        hp[c] = __float2half_rn(0.5f * x * (1.f + erff(x * 0.70710678118654752f)));
    }
}

// ---------------- launcher ----------------
extern "C" void kernel_launch(void* const* d_in, const int* in_sizes, int n_in,
                              void* d_out, int out_size)
{
    const float* x0  = (const float*)d_in[0];
    const float* x1  = (const float*)d_in[1];
    const float* Wqk = (const float*)d_in[2];
    const float* bqk = (const float*)d_in[3];
    const float* Wv  = (const float*)d_in[4];
    const float* bv  = (const float*)d_in[5];
    const float* Wo  = (const float*)d_in[6];
    const float* bo  = (const float*)d_in[7];
    const float* Wf1 = (const float*)d_in[8];
    const float* bf1 = (const float*)d_in[9];
    const float* lng = (const float*)d_in[10];
    const float* lnb = (const float*)d_in[11];
    const float* Wf2 = (const float*)d_in[12];
    const float* bf2 = (const float*)d_in[13];
    float* out = (float*)d_out;

    __half *hx0, *hx1, *qkv0, *qkv1, *ha0, *ha1, *hm0, *hm1, *hmid0, *hmid1;
    __half *hwqk, *hwv, *hwo, *hwf1, *hwf2;
    cudaGetSymbolAddress((void**)&hx0,   g_hx0);
    cudaGetSymbolAddress((void**)&hx1,   g_hx1);
    cudaGetSymbolAddress((void**)&qkv0,  g_qkv0);
    cudaGetSymbolAddress((void**)&qkv1,  g_qkv1);
    cudaGetSymbolAddress((void**)&ha0,   g_ha0);
    cudaGetSymbolAddress((void**)&ha1,   g_ha1);
    cudaGetSymbolAddress((void**)&hm0,   g_hm0);
    cudaGetSymbolAddress((void**)&hm1,   g_hm1);
    cudaGetSymbolAddress((void**)&hmid0, g_hmid0);
    cudaGetSymbolAddress((void**)&hmid1, g_hmid1);
    cudaGetSymbolAddress((void**)&hwqk,  g_hwqk);
    cudaGetSymbolAddress((void**)&hwv,   g_hwv);
    cudaGetSymbolAddress((void**)&hwo,   g_hwo);
    cudaGetSymbolAddress((void**)&hwf1,  g_hwf1);
    cudaGetSymbolAddress((void**)&hwf2,  g_hwf2);

    cudaFuncSetAttribute(gemm_h<false,true>,  cudaFuncAttributeMaxDynamicSharedMemorySize, GSMEM);
    cudaFuncSetAttribute(gemm_h<false,false>, cudaFuncAttributeMaxDynamicSharedMemorySize, GSMEM);
    cudaFuncSetAttribute(gemm_h<true,true>,   cudaFuncAttributeMaxDynamicSharedMemorySize, GSMEM);
    cudaFuncSetAttribute(attn_h, cudaFuncAttributeMaxDynamicSharedMemorySize, ATTN_SMEM);

    // fused conversions: all 7 tensors in one launch
    const long totalConv = R_END / 4;                   // float4s
    f2h_all<<<(int)((totalConv + 255) / 256), 256>>>(
        x0, x1, Wqk, Wv, Wo, Wf1, Wf2,
        hx0, hx1, hwqk, hwv, hwo, hwf1, hwf2);

    const int BIG = 1 << 28;
    dim3 gproj(FFd/128, Mrows/128, 2);   // (8, 64, 2)
    dim3 g512z(Dmod/128, Mrows/128, 2);  // (4, 64, 2)
    dim3 g1024z(FFd/128, Mrows/128, 2);  // (8, 64, 2)
    dim3 ga(Bsz*Hh, Nseq/128, 2);        // (32, 16, 2)
    dim3 gln(Mrows, 2);

    // fused QK+V projection -> qkv [M][1024]
    gemm_h<false,true><<<gproj, 256, GSMEM>>>(
        hx0, hx1, nullptr, nullptr, hwqk, hwv, bqk, bv,
        nullptr, nullptr, nullptr, nullptr, qkv0, qkv1, FFd, Dmod, Dmod);

    // cross attention (both directions)
    attn_h<<<ga, 256, ATTN_SMEM>>>(qkv0, qkv1, ha0, ha1);

    // output projection -> hm
    gemm_h<false,true><<<g512z, 256, GSMEM>>>(
        ha0, ha1, nullptr, nullptr, hwo, hwo, bo, bo,
        nullptr, nullptr, nullptr, nullptr, hm0, hm1, Dmod, Dmod, BIG);

    // FFN1 (concat fused) -> hmid
    gemm_h<true,true><<<g1024z, 256, GSMEM>>>(
        hx0, hx1, hm0, hm1, hwf1, hwf1, bf1, bf1,
        nullptr, nullptr, nullptr, nullptr, hmid0, hmid1, FFd, FFd, BIG);

    // LayerNorm + GELU
    ln_gelu_h<<<gln, 256>>>(hmid0, hmid1, lng, lnb);

    // FFN2 + residual -> out (fp32)
    gemm_h<false,false><<<g512z, 256, GSMEM>>>(
        hmid0, hmid1, nullptr, nullptr, hwf2, hwf2, bf2, bf2,
        x0, x1, out, out + (size_t)Mrows*Dmod, nullptr, nullptr, Dmod, FFd, BIG);
}

// round 15
// speedup vs baseline: 4.3218x; 1.0358x over previous
#include <cuda_runtime.h>
#include <cuda_fp16.h>
#include <math.h>
#include <stdint.h>

#define Bsz  4
#define Nseq 2048
#define Dmod 512
#define Hh   8
#define DHd  64
#define FFd  1024
#define Mrows (Bsz*Nseq)   // 8192

// ---------------- fp16 scratch ----------------
__device__ __half g_hx0  [Mrows*Dmod];
__device__ __half g_hx1  [Mrows*Dmod];
__device__ __half g_qkv0 [Mrows*FFd];   // [M][1024]: qk cols 0-511, v cols 512-1023
__device__ __half g_qkv1 [Mrows*FFd];
__device__ __half g_ha0  [Mrows*Dmod];
__device__ __half g_ha1  [Mrows*Dmod];
__device__ __half g_hm0  [Mrows*Dmod];
__device__ __half g_hm1  [Mrows*Dmod];
__device__ __half g_hmid0[Mrows*FFd];
__device__ __half g_hmid1[Mrows*FFd];
__device__ __half g_hwqk [Dmod*Dmod];
__device__ __half g_hwv  [Dmod*Dmod];
__device__ __half g_hwo  [Dmod*Dmod];
__device__ __half g_hwf1 [FFd*FFd];
__device__ __half g_hwf2 [Dmod*FFd];

// ---------------- helpers ----------------
__device__ __forceinline__ void mma_f16(float d[4], const uint32_t a[4], const uint32_t b[2]) {
    asm volatile(
        "mma.sync.aligned.m16n8k16.row.col.f32.f16.f16.f32 "
        "{%0,%1,%2,%3}, {%4,%5,%6,%7}, {%8,%9}, {%0,%1,%2,%3};\n"
        : "+f"(d[0]), "+f"(d[1]), "+f"(d[2]), "+f"(d[3])
        : "r"(a[0]), "r"(a[1]), "r"(a[2]), "r"(a[3]), "r"(b[0]), "r"(b[1]));
}
__device__ __forceinline__ void ldsm4(uint32_t r[4], uint32_t addr) {
    asm volatile("ldmatrix.sync.aligned.m8n8.x4.shared.b16 {%0,%1,%2,%3}, [%4];"
        : "=r"(r[0]), "=r"(r[1]), "=r"(r[2]), "=r"(r[3]) : "r"(addr));
}
__device__ __forceinline__ void ldsm4t(uint32_t r[4], uint32_t addr) {
    asm volatile("ldmatrix.sync.aligned.m8n8.x4.trans.shared.b16 {%0,%1,%2,%3}, [%4];"
        : "=r"(r[0]), "=r"(r[1]), "=r"(r[2]), "=r"(r[3]) : "r"(addr));
}
__device__ __forceinline__ uint32_t h2exp2(float a, float b) {
    __half2 h = __floats2half2_rn(a, b);
    uint32_t x = *(uint32_t*)&h, r;
    asm("ex2.approx.f16x2 %0, %1;" : "=r"(r) : "r"(x));
    return r;
}
__device__ __forceinline__ float fexp2(float x) {
    float r;
    asm("ex2.approx.f32 %0, %1;" : "=f"(r) : "f"(x));
    return r;
}
#define CP16(dst, src) asm volatile("cp.async.cg.shared.global [%0], [%1], 16;\n" :: "r"(dst), "l"(src))
#define CPCOMMIT()     asm volatile("cp.async.commit_group;\n" ::: "memory")
#define CPWAIT(n)      asm volatile("cp.async.wait_group %0;\n" :: "n"(n) : "memory")

// ---------------- fused f32 -> f16 conversion (all 7 tensors, one launch) ----------------
#define R_X0  0L
#define R_X1  4194304L
#define R_WQK 8388608L
#define R_WV  8650752L
#define R_WO  8912896L
#define R_WF1 9175040L
#define R_WF2 10223616L
#define R_END 10747904L
__global__ void f2h_all(
    const float* __restrict__ x0,  const float* __restrict__ x1,
    const float* __restrict__ wqk, const float* __restrict__ wv,
    const float* __restrict__ wo,  const float* __restrict__ wf1,
    const float* __restrict__ wf2,
    __half* __restrict__ hx0, __half* __restrict__ hx1,
    __half* __restrict__ hwqk, __half* __restrict__ hwv,
    __half* __restrict__ hwo, __half* __restrict__ hwf1, __half* __restrict__ hwf2)
{
    long idx = ((long)blockIdx.x * blockDim.x + threadIdx.x) * 4;
    if (idx >= R_END) return;
    const float* s; __half* d; long off;
    if      (idx < R_X1)  { s = x0;  d = hx0;  off = R_X0;  }
    else if (idx < R_WQK) { s = x1;  d = hx1;  off = R_X1;  }
    else if (idx < R_WV)  { s = wqk; d = hwqk; off = R_WQK; }
    else if (idx < R_WO)  { s = wv;  d = hwv;  off = R_WV;  }
    else if (idx < R_WF1) { s = wo;  d = hwo;  off = R_WO;  }
    else if (idx < R_WF2) { s = wf1; d = hwf1; off = R_WF1; }
    else                  { s = wf2; d = hwf2; off = R_WF2; }
    long i = idx - off;
    float4 v = *(const float4*)(s + i);
    __half2* dp = (__half2*)(d + i);
    dp[0] = __floats2half2_rn(v.x, v.y);
    dp[1] = __floats2half2_rn(v.z, v.w);
}

// ---------------- FP16 GEMM: cp.async 3-stage + ldmatrix, m16n8k16, 2-stream ----------------
#define GSMEM 98304
template<bool CAT, bool OUTH>
__global__ __launch_bounds__(256, 2) void gemm_h(
    const __half* __restrict__ A0, const __half* __restrict__ A1,
    const __half* __restrict__ A20, const __half* __restrict__ A21,
    const __half* __restrict__ Wa, const __half* __restrict__ Wb,
    const float* __restrict__ biasa, const float* __restrict__ biasb,
    const float* __restrict__ res0, const float* __restrict__ res1,
    float* __restrict__ Cf0, float* __restrict__ Cf1,
    __half* __restrict__ Ch0, __half* __restrict__ Ch1,
    int N, int K, int NS)
{
    extern __shared__ float sm[];
    const uint32_t smB = (uint32_t)__cvta_generic_to_shared(sm);

    const int z = blockIdx.z;
    const __half* A   = z ? A1  : A0;
    const __half* A2  = z ? A21 : A20;
    const float*  res = z ? res1 : res0;
    float*  Cf = z ? Cf1 : Cf0;
    __half* Ch = z ? Ch1 : Ch0;

    const int tid  = threadIdx.x;
    const int wid  = tid >> 5, lane = tid & 31;
    const int g    = lane >> 2, tig = lane & 3;
    const int wm   = wid & 1,  wn   = wid >> 1;
    const int lr   = tid >> 3;
    const int lu   = tid & 7;
    const int j    = lane >> 3;
    const int jr   = (j & 1) * 8, jc = (j >> 1);
    const int l7   = lane & 7;

    const int arow0 = blockIdx.y * 128;
    const int brow0 = blockIdx.x * 128;

    const __half* Wsel = (brow0 < NS) ? (Wa + (size_t)brow0 * K) : (Wb + (size_t)(brow0 - NS) * K);
    const float* biasSel = (brow0 < NS) ? biasa : biasb;
    const int coff = (brow0 < NS) ? 0 : NS;

    uint32_t rbA[4], rbB[2];
    #pragma unroll
    for (int m = 0; m < 4; m++) rbA[m] = (uint32_t)(wm*64 + m*16 + jr + l7) * 128u;
    #pragma unroll
    for (int np = 0; np < 2; np++) rbB[np] = (uint32_t)(wn*32 + np*16 + jr + l7) * 128u;

    const uint32_t cpOff = (uint32_t)(lr * 128 + ((lu ^ (lr & 7)) << 4));

    float acc[4][4][4];
    #pragma unroll
    for (int m = 0; m < 4; m++)
        #pragma unroll
        for (int n = 0; n < 4; n++)
            #pragma unroll
            for (int q = 0; q < 4; q++) acc[m][n][q] = 0.f;

    const int T = K / 64;

    auto issue = [&](int t, int s) {
        const int colg = t*64 + lu*8;
        const uint32_t dstA = smB + (uint32_t)s*32768u + cpOff;
        const uint32_t dstB = dstA + 16384u;
        #pragma unroll
        for (int i = 0; i < 4; i++) {
            int row = lr + 32*i;
            const __half* srcA;
            if (CAT) {
                srcA = (colg < 512) ? (A  + (size_t)(arow0+row)*512 + colg)
                                    : (A2 + (size_t)(arow0+row)*512 + colg - 512);
            } else {
                srcA = A + (size_t)(arow0+row)*K + colg;
            }
            CP16(dstA + i*4096u, srcA);
            CP16(dstB + i*4096u, Wsel + (size_t)row*K + colg);
        }
        CPCOMMIT();
    };

    issue(0, 0);
    issue(1, 1);
    int so = 0;

    for (int t = 0; t < T; t++) {
        if (t + 1 < T) { CPWAIT(1); } else { CPWAIT(0); }
        __syncthreads();
        if (t + 2 < T) {
            int s = so + 2;
            if (s >= 3) s -= 3;
            issue(t + 2, s);
        }

        const uint32_t aB = smB + (uint32_t)so * 32768u;
        const uint32_t bB = aB + 16384u;

        #pragma unroll
        for (int kk = 0; kk < 4; kk++) {
            const uint32_t xofs = (uint32_t)((((kk << 1) | jc) ^ l7) << 4);
            uint32_t af[4][4], bf[4][2];
            #pragma unroll
            for (int m = 0; m < 4; m++)
                ldsm4(af[m], aB + rbA[m] + xofs);
            #pragma unroll
            for (int np = 0; np < 2; np++) {
                uint32_t t4[4];
                ldsm4(t4, bB + rbB[np] + xofs);
                bf[2*np  ][0] = t4[0]; bf[2*np  ][1] = t4[2];
                bf[2*np+1][0] = t4[1]; bf[2*np+1][1] = t4[3];
            }
            #pragma unroll
            for (int m = 0; m < 4; m++)
                #pragma unroll
                for (int n = 0; n < 4; n++)
                    mma_f16(acc[m][n], af[m], bf[n]);
        }
        so = (so == 2) ? 0 : so + 1;
    }

    const int rb = arow0 + wm * 64;
    const int cb = brow0 + wn * 32;
    #pragma unroll
    for (int m = 0; m < 4; m++) {
        #pragma unroll
        for (int n = 0; n < 4; n++) {
            int row0 = rb + m*16 + g;
            int col  = cb + n*8 + tig*2;
            float b0 = biasSel[col - coff], b1 = biasSel[col - coff + 1];
            float v0 = acc[m][n][0] + b0, v1 = acc[m][n][1] + b1;
            float v2 = acc[m][n][2] + b0, v3 = acc[m][n][3] + b1;
            if (OUTH) {
                *(__half2*)(Ch + (size_t)row0     * N + col) = __floats2half2_rn(v0, v1);
                *(__half2*)(Ch + (size_t)(row0+8) * N + col) = __floats2half2_rn(v2, v3);
            } else {
                if (res) {
                    const float* r0p = res + (size_t)row0 * N + col;
                    const float* r1p = res + (size_t)(row0+8) * N + col;
                    v0 += r0p[0]; v1 += r0p[1];
                    v2 += r1p[0]; v3 += r1p[1];
                }
                *(float2*)(Cf + (size_t)row0     * N + col) = make_float2(v0, v1);
                *(float2*)(Cf + (size_t)(row0+8) * N + col) = make_float2(v2, v3);
            }
        }
    }
}

// ---------------- FP16 flash attention: log2-domain softmax, f16x2 exp, mma row sums ----------------
#define KT 64
#define ATTN_SMEM 32768
#define LQ 1024

__global__ __launch_bounds__(256) void attn_h(
    const __half* __restrict__ qkv0, const __half* __restrict__ qkv1,
    __half* __restrict__ O0, __half* __restrict__ O1)
{
    extern __shared__ float smbuf[];
    const uint32_t smB = (uint32_t)__cvta_generic_to_shared(smbuf);

    const int z = blockIdx.z;
    const __half* Qb = z ? qkv1 : qkv0;
    const __half* Kb = z ? qkv0 : qkv1;
    __half* Ob = z ? O1 : O0;

    const int tid  = threadIdx.x;
    const int wid  = tid >> 5, lane = tid & 31;
    const int g    = lane >> 2, tig = lane & 3;
    const int j    = lane >> 3;
    const int jr   = (j & 1) * 8, jc = (j >> 1);
    const int l7   = lane & 7;

    const int bh = blockIdx.x;
    const int b  = bh >> 3, h = bh & 7;
    const size_t qbase = (size_t)b * (Nseq * LQ) + (size_t)h * DHd;
    const int qrow = blockIdx.y * 128 + wid * 16;

    // Q fragments, pre-scaled by 0.125*log2(e) -> scores in log2 domain
    uint32_t qf[4][4];
    {
        const __half* qp = Qb + qbase + (size_t)(qrow + g) * LQ;
        const __half2 sc = __float2half2_rn(0.18033688f);
        #pragma unroll
        for (int ks = 0; ks < 4; ks++) {
            __half2 q0 = *(const __half2*)(qp + ks*16 + tig*2);
            __half2 q1 = *(const __half2*)(qp + 8*LQ + ks*16 + tig*2);
            __half2 q2 = *(const __half2*)(qp + ks*16 + 8 + tig*2);
            __half2 q3 = *(const __half2*)(qp + 8*LQ + ks*16 + 8 + tig*2);
            q0 = __hmul2(q0, sc); q1 = __hmul2(q1, sc);
            q2 = __hmul2(q2, sc); q3 = __hmul2(q3, sc);
            qf[ks][0] = *(uint32_t*)&q0; qf[ks][1] = *(uint32_t*)&q1;
            qf[ks][2] = *(uint32_t*)&q2; qf[ks][3] = *(uint32_t*)&q3;
        }
    }

    float oacc[8][4];
    #pragma unroll
    for (int n = 0; n < 8; n++)
        #pragma unroll
        for (int q = 0; q < 4; q++) oacc[n][q] = 0.f;
    float lacc[4] = {0.f, 0.f, 0.f, 0.f};          // ones-column row-sum accumulator
    float m0 = -1e30f, m1 = -1e30f;

    const int lr = tid >> 3;
    const int lu = tid & 7;
    const __half* Kg = Kb + qbase + (size_t)lr * LQ + lu*8;
    const __half* Vg = Kg + 512;

    const uint32_t kvOff = (uint32_t)(lr * 128 + ((lu ^ (lr & 7)) << 4));
    auto issueKV = [&](int kt) {
        const int s = kt & 1;
        const size_t off = (size_t)kt * KT * LQ;
        const uint32_t kd = smB + (uint32_t)s * 16384u + kvOff;
        const uint32_t vd = kd + 8192u;
        CP16(kd,          Kg + off);
        CP16(kd + 4096u,  Kg + off + 32*LQ);
        CP16(vd,          Vg + off);
        CP16(vd + 4096u,  Vg + off + 32*LQ);
        CPCOMMIT();
    };

    const uint32_t bones[2] = { 0x3C003C00u, 0x3C003C00u };   // half2(1,1) x2

    issueKV(0);
    const int TKT = Nseq / KT;
    for (int kt = 0; kt < TKT; kt++) {
        if (kt + 1 < TKT) { issueKV(kt + 1); CPWAIT(1); } else { CPWAIT(0); }
        __syncthreads();

        const uint32_t Kst = smB + (uint32_t)(kt & 1) * 16384u;
        const uint32_t Vst = Kst + 8192u;

        float sacc[8][4];
        #pragma unroll
        for (int n = 0; n < 8; n++)
            #pragma unroll
            for (int q = 0; q < 4; q++) sacc[n][q] = 0.f;

        #pragma unroll
        for (int kk = 0; kk < 4; kk++) {
            const uint32_t xofs = (uint32_t)((((kk << 1) | jc) ^ l7) << 4);
            uint32_t bf[8][2];
            #pragma unroll
            for (int p = 0; p < 4; p++) {
                uint32_t t4[4];
                ldsm4(t4, Kst + (uint32_t)((p*16 + jr + l7) * 128) + xofs);
                bf[2*p  ][0] = t4[0]; bf[2*p  ][1] = t4[2];
                bf[2*p+1][0] = t4[1]; bf[2*p+1][1] = t4[3];
            }
            #pragma unroll
            for (int n = 0; n < 8; n++) mma_f16(sacc[n], qf[kk], bf[n]);
        }

        // online softmax, log2 domain
        float t0 = -1e30f, t1 = -1e30f;
        #pragma unroll
        for (int n = 0; n < 8; n++) {
            t0 = fmaxf(t0, fmaxf(sacc[n][0], sacc[n][1]));
            t1 = fmaxf(t1, fmaxf(sacc[n][2], sacc[n][3]));
        }
        t0 = fmaxf(t0, __shfl_xor_sync(0xffffffffu, t0, 1));
        t0 = fmaxf(t0, __shfl_xor_sync(0xffffffffu, t0, 2));
        t1 = fmaxf(t1, __shfl_xor_sync(0xffffffffu, t1, 1));
        t1 = fmaxf(t1, __shfl_xor_sync(0xffffffffu, t1, 2));

        float mn0 = fmaxf(m0, t0), mn1 = fmaxf(m1, t1);
        float c0 = fexp2(m0 - mn0), c1 = fexp2(m1 - mn1);
        m0 = mn0; m1 = mn1;

        // P = exp2(s - m) in packed half2 (A-fragment format)
        uint32_t ph0[8], ph1[8];
        #pragma unroll
        for (int n = 0; n < 8; n++) {
            ph0[n] = h2exp2(sacc[n][0] - m0, sacc[n][1] - m0);
            ph1[n] = h2exp2(sacc[n][2] - m1, sacc[n][3] - m1);
        }

        // rescale accumulators
        #pragma unroll
        for (int n = 0; n < 8; n++) {
            oacc[n][0] *= c0; oacc[n][1] *= c0;
            oacc[n][2] *= c1; oacc[n][3] *= c1;
        }
        lacc[0] *= c0; lacc[1] *= c0;
        lacc[2] *= c1; lacc[3] *= c1;

        // O += P V ; l += P @ ones
        #pragma unroll
        for (int ks = 0; ks < 4; ks++) {
            uint32_t af[4];
            af[0] = ph0[2*ks];   af[1] = ph1[2*ks];
            af[2] = ph0[2*ks+1]; af[3] = ph1[2*ks+1];
            mma_f16(lacc, af, bones);
            const uint32_t vrow = (uint32_t)((ks*16 + jr + l7) * 128);
            #pragma unroll
            for (int p = 0; p < 4; p++) {
                uint32_t t4[4];
                ldsm4t(t4, Vst + vrow + (uint32_t)((((p << 1) | jc) ^ l7) << 4));
                uint32_t bv0[2] = { t4[0], t4[1] };
                uint32_t bv1[2] = { t4[2], t4[3] };
                mma_f16(oacc[2*p  ], af, bv0);
                mma_f16(oacc[2*p+1], af, bv1);
            }
        }
        __syncthreads();
    }

    float i0 = 1.f / lacc[0], i1 = 1.f / lacc[2];
    __half* Op = Ob + (size_t)b * (Nseq * Dmod) + (size_t)h * DHd + (size_t)(qrow + g) * Dmod;
    #pragma unroll
    for (int n = 0; n < 8; n++) {
        *(__half2*)(Op + n*8 + tig*2)          = __floats2half2_rn(oacc[n][0]*i0, oacc[n][1]*i0);
        *(__half2*)(Op + 8*Dmod + n*8 + tig*2) = __floats2half2_rn(oacc[n][2]*i1, oacc[n][3]*i1);
    }
}

// ---------------- LayerNorm(1024) + exact GELU, fp16, 2-stream ----------------
__global__ __launch_bounds__(256) void ln_gelu_h(
    __half* __restrict__ Hm0, __half* __restrict__ Hm1,
    const float* __restrict__ gw, const float* __restrict__ bw)
{
    __shared__ float red1[8];
    __shared__ float red2[8];
    __shared__ float s_mu, s_inv;

    const int row = blockIdx.x;
    const int tid = threadIdx.x;
    __half* hp = (blockIdx.y ? Hm1 : Hm0) + (size_t)row * FFd;

    float v[4];
    float s = 0.f;
    #pragma unroll
    for (int i = 0; i < 4; i++) { v[i] = __half2float(hp[tid + i*256]); s += v[i]; }

    #pragma unroll
    for (int off = 16; off; off >>= 1) s += __shfl_xor_sync(0xffffffffu, s, off);
    if ((tid & 31) == 0) red1[tid >> 5] = s;
    __syncthreads();
    if (tid == 0) {
        float t = 0.f;
        #pragma unroll
        for (int w = 0; w < 8; w++) t += red1[w];
        s_mu = t * (1.f / FFd);
    }
    __syncthreads();
    const float mu = s_mu;

    float ss = 0.f;
    #pragma unroll
    for (int i = 0; i < 4; i++) { float d = v[i] - mu; ss += d*d; }
    #pragma unroll
    for (int off = 16; off; off >>= 1) ss += __shfl_xor_sync(0xffffffffu, ss, off);
    if ((tid & 31) == 0) red2[tid >> 5] = ss;
    __syncthreads();
    if (tid == 0) {
        float t = 0.f;
        #pragma unroll
        for (int w = 0; w < 8; w++) t += red2[w];
        s_inv = rsqrtf(t * (1.f / FFd) + 1e-5f);
    }
    __syncthreads();
    const float inv = s_inv;

    #pragma unroll
    for (int i = 0; i < 4; i++) {
        int c = tid + i*256;
        float x = (v[i] - mu) * inv * gw[c] + bw[c];
        hp[c] = __float2half_rn(0.5f * x * (1.f + erff(x * 0.70710678118654752f)));
    }
}

// ---------------- launcher ----------------
extern "C" void kernel_launch(void* const* d_in, const int* in_sizes, int n_in,
                              void* d_out, int out_size)
{
    const float* x0  = (const float*)d_in[0];
    const float* x1  = (const float*)d_in[1];
    const float* Wqk = (const float*)d_in[2];
    const float* bqk = (const float*)d_in[3];
    const float* Wv  = (const float*)d_in[4];
    const float* bv  = (const float*)d_in[5];
    const float* Wo  = (const float*)d_in[6];
    const float* bo  = (const float*)d_in[7];
    const float* Wf1 = (const float*)d_in[8];
    const float* bf1 = (const float*)d_in[9];
    const float* lng = (const float*)d_in[10];
    const float* lnb = (const float*)d_in[11];
    const float* Wf2 = (const float*)d_in[12];
    const float* bf2 = (const float*)d_in[13];
    float* out = (float*)d_out;

    __half *hx0, *hx1, *qkv0, *qkv1, *ha0, *ha1, *hm0, *hm1, *hmid0, *hmid1;
    __half *hwqk, *hwv, *hwo, *hwf1, *hwf2;
    cudaGetSymbolAddress((void**)&hx0,   g_hx0);
    cudaGetSymbolAddress((void**)&hx1,   g_hx1);
    cudaGetSymbolAddress((void**)&qkv0,  g_qkv0);
    cudaGetSymbolAddress((void**)&qkv1,  g_qkv1);
    cudaGetSymbolAddress((void**)&ha0,   g_ha0);
    cudaGetSymbolAddress((void**)&ha1,   g_ha1);
    cudaGetSymbolAddress((void**)&hm0,   g_hm0);
    cudaGetSymbolAddress((void**)&hm1,   g_hm1);
    cudaGetSymbolAddress((void**)&hmid0, g_hmid0);
    cudaGetSymbolAddress((void**)&hmid1, g_hmid1);
    cudaGetSymbolAddress((void**)&hwqk,  g_hwqk);
    cudaGetSymbolAddress((void**)&hwv,   g_hwv);
    cudaGetSymbolAddress((void**)&hwo,   g_hwo);
    cudaGetSymbolAddress((void**)&hwf1,  g_hwf1);
    cudaGetSymbolAddress((void**)&hwf2,  g_hwf2);

    cudaFuncSetAttribute(gemm_h<false,true>,  cudaFuncAttributeMaxDynamicSharedMemorySize, GSMEM);
    cudaFuncSetAttribute(gemm_h<false,false>, cudaFuncAttributeMaxDynamicSharedMemorySize, GSMEM);
    cudaFuncSetAttribute(gemm_h<true,true>,   cudaFuncAttributeMaxDynamicSharedMemorySize, GSMEM);
    cudaFuncSetAttribute(attn_h, cudaFuncAttributeMaxDynamicSharedMemorySize, ATTN_SMEM);

    const long totalConv = R_END / 4;
    f2h_all<<<(int)((totalConv + 255) / 256), 256>>>(
        x0, x1, Wqk, Wv, Wo, Wf1, Wf2,
        hx0, hx1, hwqk, hwv, hwo, hwf1, hwf2);

    const int BIG = 1 << 28;
    dim3 gproj(FFd/128, Mrows/128, 2);
    dim3 g512z(Dmod/128, Mrows/128, 2);
    dim3 g1024z(FFd/128, Mrows/128, 2);
    dim3 ga(Bsz*Hh, Nseq/128, 2);
    dim3 gln(Mrows, 2);

    // fused QK+V projection -> qkv [M][1024]
    gemm_h<false,true><<<gproj, 256, GSMEM>>>(
        hx0, hx1, nullptr, nullptr, hwqk, hwv, bqk, bv,
        nullptr, nullptr, nullptr, nullptr, qkv0, qkv1, FFd, Dmod, Dmod);

    // cross attention (both directions)
    attn_h<<<ga, 256, ATTN_SMEM>>>(qkv0, qkv1, ha0, ha1);

    // output projection -> hm
    gemm_h<false,true><<<g512z, 256, GSMEM>>>(
        ha0, ha1, nullptr, nullptr, hwo, hwo, bo, bo,
        nullptr, nullptr, nullptr, nullptr, hm0, hm1, Dmod, Dmod, BIG);

    // FFN1 (concat fused) -> hmid
    gemm_h<true,true><<<g1024z, 256, GSMEM>>>(
        hx0, hx1, hm0, hm1, hwf1, hwf1, bf1, bf1,
        nullptr, nullptr, nullptr, nullptr, hmid0, hmid1, FFd, FFd, BIG);

    // LayerNorm + GELU
    ln_gelu_h<<<gln, 256>>>(hmid0, hmid1, lng, lnb);

    // FFN2 + residual -> out (fp32)
    gemm_h<false,false><<<g512z, 256, GSMEM>>>(
        hmid0, hmid1, nullptr, nullptr, hwf2, hwf2, bf2, bf2,
        x0, x1, out, out + (size_t)Mrows*Dmod, nullptr, nullptr, Dmod, FFd, BIG);
}

// round 17
// speedup vs baseline: 4.4375x; 1.0268x over previous
#include <cuda_runtime.h>
#include <cuda_fp16.h>
#include <math.h>
#include <stdint.h>

#define Bsz  4
#define Nseq 2048
#define Dmod 512
#define Hh   8
#define DHd  64
#define FFd  1024
#define Mrows (Bsz*Nseq)   // 8192

// ---------------- fp16 scratch ----------------
__device__ __half g_hx0  [Mrows*Dmod];
__device__ __half g_hx1  [Mrows*Dmod];
__device__ __half g_qkv0 [Mrows*FFd];   // [M][1024]: qk cols 0-511, v cols 512-1023
__device__ __half g_qkv1 [Mrows*FFd];
__device__ __half g_ha0  [Mrows*Dmod];
__device__ __half g_ha1  [Mrows*Dmod];
__device__ __half g_hm0  [Mrows*Dmod];
__device__ __half g_hm1  [Mrows*Dmod];
__device__ __half g_hmid0[Mrows*FFd];
__device__ __half g_hmid1[Mrows*FFd];
__device__ __half g_hwqk [Dmod*Dmod];
__device__ __half g_hwv  [Dmod*Dmod];
__device__ __half g_hwo  [Dmod*Dmod];
__device__ __half g_hwf1 [FFd*FFd];
__device__ __half g_hwf2 [Dmod*FFd];

// ---------------- helpers ----------------
__device__ __forceinline__ void mma_f16(float d[4], const uint32_t a[4], const uint32_t b[2]) {
    asm volatile(
        "mma.sync.aligned.m16n8k16.row.col.f32.f16.f16.f32 "
        "{%0,%1,%2,%3}, {%4,%5,%6,%7}, {%8,%9}, {%0,%1,%2,%3};\n"
        : "+f"(d[0]), "+f"(d[1]), "+f"(d[2]), "+f"(d[3])
        : "r"(a[0]), "r"(a[1]), "r"(a[2]), "r"(a[3]), "r"(b[0]), "r"(b[1]));
}
__device__ __forceinline__ void ldsm4(uint32_t r[4], uint32_t addr) {
    asm volatile("ldmatrix.sync.aligned.m8n8.x4.shared.b16 {%0,%1,%2,%3}, [%4];"
        : "=r"(r[0]), "=r"(r[1]), "=r"(r[2]), "=r"(r[3]) : "r"(addr));
}
__device__ __forceinline__ void ldsm4t(uint32_t r[4], uint32_t addr) {
    asm volatile("ldmatrix.sync.aligned.m8n8.x4.trans.shared.b16 {%0,%1,%2,%3}, [%4];"
        : "=r"(r[0]), "=r"(r[1]), "=r"(r[2]), "=r"(r[3]) : "r"(addr));
}
__device__ __forceinline__ uint32_t h2exp2(float a, float b) {
    __half2 h = __floats2half2_rn(a, b);
    uint32_t x = *(uint32_t*)&h, r;
    asm("ex2.approx.f16x2 %0, %1;" : "=r"(r) : "r"(x));
    return r;
}
__device__ __forceinline__ float fexp2(float x) {
    float r;
    asm("ex2.approx.f32 %0, %1;" : "=f"(r) : "f"(x));
    return r;
}
#define CP16(dst, src) asm volatile("cp.async.cg.shared.global [%0], [%1], 16;\n" :: "r"(dst), "l"(src))
#define CPCOMMIT()     asm volatile("cp.async.commit_group;\n" ::: "memory")
#define CPWAIT(n)      asm volatile("cp.async.wait_group %0;\n" :: "n"(n) : "memory")

// ---------------- fused f32 -> f16 conversion (all 7 tensors, one launch) ----------------
#define R_X0  0L
#define R_X1  4194304L
#define R_WQK 8388608L
#define R_WV  8650752L
#define R_WO  8912896L
#define R_WF1 9175040L
#define R_WF2 10223616L
#define R_END 10747904L
__global__ void f2h_all(
    const float* __restrict__ x0,  const float* __restrict__ x1,
    const float* __restrict__ wqk, const float* __restrict__ wv,
    const float* __restrict__ wo,  const float* __restrict__ wf1,
    const float* __restrict__ wf2,
    __half* __restrict__ hx0, __half* __restrict__ hx1,
    __half* __restrict__ hwqk, __half* __restrict__ hwv,
    __half* __restrict__ hwo, __half* __restrict__ hwf1, __half* __restrict__ hwf2)
{
    long idx = ((long)blockIdx.x * blockDim.x + threadIdx.x) * 4;
    if (idx >= R_END) return;
    const float* s; __half* d; long off;
    if      (idx < R_X1)  { s = x0;  d = hx0;  off = R_X0;  }
    else if (idx < R_WQK) { s = x1;  d = hx1;  off = R_X1;  }
    else if (idx < R_WV)  { s = wqk; d = hwqk; off = R_WQK; }
    else if (idx < R_WO)  { s = wv;  d = hwv;  off = R_WV;  }
    else if (idx < R_WF1) { s = wo;  d = hwo;  off = R_WO;  }
    else if (idx < R_WF2) { s = wf1; d = hwf1; off = R_WF1; }
    else                  { s = wf2; d = hwf2; off = R_WF2; }
    long i = idx - off;
    float4 v = *(const float4*)(s + i);
    __half2* dp = (__half2*)(d + i);
    dp[0] = __floats2half2_rn(v.x, v.y);
    dp[1] = __floats2half2_rn(v.z, v.w);
}

// ---------------- FP16 GEMM: cp.async 3-stage + ldmatrix, m16n8k16, 2-stream ----------------
#define GSMEM 98304
template<bool CAT, bool OUTH>
__global__ __launch_bounds__(256, 2) void gemm_h(
    const __half* __restrict__ A0, const __half* __restrict__ A1,
    const __half* __restrict__ A20, const __half* __restrict__ A21,
    const __half* __restrict__ Wa, const __half* __restrict__ Wb,
    const float* __restrict__ biasa, const float* __restrict__ biasb,
    const float* __restrict__ res0, const float* __restrict__ res1,
    float* __restrict__ Cf0, float* __restrict__ Cf1,
    __half* __restrict__ Ch0, __half* __restrict__ Ch1,
    int N, int K, int NS)
{
    extern __shared__ float sm[];
    const uint32_t smB = (uint32_t)__cvta_generic_to_shared(sm);

    const int z = blockIdx.z;
    const __half* A   = z ? A1  : A0;
    const __half* A2  = z ? A21 : A20;
    const float*  res = z ? res1 : res0;
    float*  Cf = z ? Cf1 : Cf0;
    __half* Ch = z ? Ch1 : Ch0;

    const int tid  = threadIdx.x;
    const int wid  = tid >> 5, lane = tid & 31;
    const int g    = lane >> 2, tig = lane & 3;
    const int wm   = wid & 1,  wn   = wid >> 1;
    const int lr   = tid >> 3;
    const int lu   = tid & 7;
    const int j    = lane >> 3;
    const int jr   = (j & 1) * 8, jc = (j >> 1);
    const int l7   = lane & 7;

    const int arow0 = blockIdx.y * 128;
    const int brow0 = blockIdx.x * 128;

    const __half* Wsel = (brow0 < NS) ? (Wa + (size_t)brow0 * K) : (Wb + (size_t)(brow0 - NS) * K);
    const float* biasSel = (brow0 < NS) ? biasa : biasb;
    const int coff = (brow0 < NS) ? 0 : NS;

    uint32_t rbA[4], rbB[2];
    #pragma unroll
    for (int m = 0; m < 4; m++) rbA[m] = (uint32_t)(wm*64 + m*16 + jr + l7) * 128u;
    #pragma unroll
    for (int np = 0; np < 2; np++) rbB[np] = (uint32_t)(wn*32 + np*16 + jr + l7) * 128u;

    const uint32_t cpOff = (uint32_t)(lr * 128 + ((lu ^ (lr & 7)) << 4));

    float acc[4][4][4];
    #pragma unroll
    for (int m = 0; m < 4; m++)
        #pragma unroll
        for (int n = 0; n < 4; n++)
            #pragma unroll
            for (int q = 0; q < 4; q++) acc[m][n][q] = 0.f;

    const int T = K / 64;

    auto issue = [&](int t, int s) {
        const int colg = t*64 + lu*8;
        const uint32_t dstA = smB + (uint32_t)s*32768u + cpOff;
        const uint32_t dstB = dstA + 16384u;
        #pragma unroll
        for (int i = 0; i < 4; i++) {
            int row = lr + 32*i;
            const __half* srcA;
            if (CAT) {
                srcA = (colg < 512) ? (A  + (size_t)(arow0+row)*512 + colg)
                                    : (A2 + (size_t)(arow0+row)*512 + colg - 512);
            } else {
                srcA = A + (size_t)(arow0+row)*K + colg;
            }
            CP16(dstA + i*4096u, srcA);
            CP16(dstB + i*4096u, Wsel + (size_t)row*K + colg);
        }
        CPCOMMIT();
    };

    issue(0, 0);
    issue(1, 1);
    int so = 0;

    for (int t = 0; t < T; t++) {
        if (t + 1 < T) { CPWAIT(1); } else { CPWAIT(0); }
        __syncthreads();
        if (t + 2 < T) {
            int s = so + 2;
            if (s >= 3) s -= 3;
            issue(t + 2, s);
        }

        const uint32_t aB = smB + (uint32_t)so * 32768u;
        const uint32_t bB = aB + 16384u;

        #pragma unroll
        for (int kk = 0; kk < 4; kk++) {
            const uint32_t xofs = (uint32_t)((((kk << 1) | jc) ^ l7) << 4);
            uint32_t af[4][4], bf[4][2];
            #pragma unroll
            for (int m = 0; m < 4; m++)
                ldsm4(af[m], aB + rbA[m] + xofs);
            #pragma unroll
            for (int np = 0; np < 2; np++) {
                uint32_t t4[4];
                ldsm4(t4, bB + rbB[np] + xofs);
                bf[2*np  ][0] = t4[0]; bf[2*np  ][1] = t4[2];
                bf[2*np+1][0] = t4[1]; bf[2*np+1][1] = t4[3];
            }
            #pragma unroll
            for (int m = 0; m < 4; m++)
                #pragma unroll
                for (int n = 0; n < 4; n++)
                    mma_f16(acc[m][n], af[m], bf[n]);
        }
        so = (so == 2) ? 0 : so + 1;
    }

    const int rb = arow0 + wm * 64;
    const int cb = brow0 + wn * 32;
    #pragma unroll
    for (int m = 0; m < 4; m++) {
        #pragma unroll
        for (int n = 0; n < 4; n++) {
            int row0 = rb + m*16 + g;
            int col  = cb + n*8 + tig*2;
            float b0 = biasSel[col - coff], b1 = biasSel[col - coff + 1];
            float v0 = acc[m][n][0] + b0, v1 = acc[m][n][1] + b1;
            float v2 = acc[m][n][2] + b0, v3 = acc[m][n][3] + b1;
            if (OUTH) {
                *(__half2*)(Ch + (size_t)row0     * N + col) = __floats2half2_rn(v0, v1);
                *(__half2*)(Ch + (size_t)(row0+8) * N + col) = __floats2half2_rn(v2, v3);
            } else {
                if (res) {
                    const float* r0p = res + (size_t)row0 * N + col;
                    const float* r1p = res + (size_t)(row0+8) * N + col;
                    v0 += r0p[0]; v1 += r0p[1];
                    v2 += r1p[0]; v3 += r1p[1];
                }
                *(float2*)(Cf + (size_t)row0     * N + col) = make_float2(v0, v1);
                *(float2*)(Cf + (size_t)(row0+8) * N + col) = make_float2(v2, v3);
            }
        }
    }
}

// ---------------- FP16 flash attention: 3-stage KV ring, 1 sync/tile, 2 CTAs/SM ----------------
// smem bytes: stage s (0..2): K @ s*16384, V @ s*16384+8192.  (48 KB)
#define KT 64
#define ATTN_SMEM 49152
#define LQ 1024

__global__ __launch_bounds__(256, 2) void attn_h(
    const __half* __restrict__ qkv0, const __half* __restrict__ qkv1,
    __half* __restrict__ O0, __half* __restrict__ O1)
{
    extern __shared__ float smbuf[];
    const uint32_t smB = (uint32_t)__cvta_generic_to_shared(smbuf);

    const int z = blockIdx.z;
    const __half* Qb = z ? qkv1 : qkv0;
    const __half* Kb = z ? qkv0 : qkv1;
    __half* Ob = z ? O1 : O0;

    const int tid  = threadIdx.x;
    const int wid  = tid >> 5, lane = tid & 31;
    const int g    = lane >> 2, tig = lane & 3;
    const int j    = lane >> 3;
    const int jr   = (j & 1) * 8, jc = (j >> 1);
    const int l7   = lane & 7;

    const int bh = blockIdx.x;
    const int b  = bh >> 3, h = bh & 7;
    const size_t qbase = (size_t)b * (Nseq * LQ) + (size_t)h * DHd;
    const int qrow = blockIdx.y * 128 + wid * 16;

    // Q fragments, pre-scaled by 0.125*log2(e) -> scores in log2 domain
    uint32_t qf[4][4];
    {
        const __half* qp = Qb + qbase + (size_t)(qrow + g) * LQ;
        const __half2 sc = __float2half2_rn(0.18033688f);
        #pragma unroll
        for (int ks = 0; ks < 4; ks++) {
            __half2 q0 = *(const __half2*)(qp + ks*16 + tig*2);
            __half2 q1 = *(const __half2*)(qp + 8*LQ + ks*16 + tig*2);
            __half2 q2 = *(const __half2*)(qp + ks*16 + 8 + tig*2);
            __half2 q3 = *(const __half2*)(qp + 8*LQ + ks*16 + 8 + tig*2);
            q0 = __hmul2(q0, sc); q1 = __hmul2(q1, sc);
            q2 = __hmul2(q2, sc); q3 = __hmul2(q3, sc);
            qf[ks][0] = *(uint32_t*)&q0; qf[ks][1] = *(uint32_t*)&q1;
            qf[ks][2] = *(uint32_t*)&q2; qf[ks][3] = *(uint32_t*)&q3;
        }
    }

    float oacc[8][4];
    #pragma unroll
    for (int n = 0; n < 8; n++)
        #pragma unroll
        for (int q = 0; q < 4; q++) oacc[n][q] = 0.f;
    float lacc[4] = {0.f, 0.f, 0.f, 0.f};
    float m0 = -1e30f, m1 = -1e30f;

    const int lr = tid >> 3;
    const int lu = tid & 7;
    const __half* Kg = Kb + qbase + (size_t)lr * LQ + lu*8;
    const __half* Vg = Kg + 512;

    const uint32_t kvOff = (uint32_t)(lr * 128 + ((lu ^ (lr & 7)) << 4));
    auto issueKV = [&](int kt, int s) {
        const size_t off = (size_t)kt * KT * LQ;
        const uint32_t kd = smB + (uint32_t)s * 16384u + kvOff;
        const uint32_t vd = kd + 8192u;
        CP16(kd,          Kg + off);
        CP16(kd + 4096u,  Kg + off + 32*LQ);
        CP16(vd,          Vg + off);
        CP16(vd + 4096u,  Vg + off + 32*LQ);
        CPCOMMIT();
    };

    const uint32_t bones[2] = { 0x3C003C00u, 0x3C003C00u };   // half2(1,1) x2

    issueKV(0, 0);
    issueKV(1, 1);
    int so = 0;
    const int TKT = Nseq / KT;
    for (int kt = 0; kt < TKT; kt++) {
        if (kt + 1 < TKT) { CPWAIT(1); } else { CPWAIT(0); }
        __syncthreads();                       // all warps done with stage (kt-1)%3; stage kt%3 ready
        if (kt + 2 < TKT) {
            int s = so + 2;
            if (s >= 3) s -= 3;
            issueKV(kt + 2, s);
        }

        const uint32_t Kst = smB + (uint32_t)so * 16384u;
        const uint32_t Vst = Kst + 8192u;

        float sacc[8][4];
        #pragma unroll
        for (int n = 0; n < 8; n++)
            #pragma unroll
            for (int q = 0; q < 4; q++) sacc[n][q] = 0.f;

        #pragma unroll
        for (int kk = 0; kk < 4; kk++) {
            const uint32_t xofs = (uint32_t)((((kk << 1) | jc) ^ l7) << 4);
            uint32_t bf[8][2];
            #pragma unroll
            for (int p = 0; p < 4; p++) {
                uint32_t t4[4];
                ldsm4(t4, Kst + (uint32_t)((p*16 + jr + l7) * 128) + xofs);
                bf[2*p  ][0] = t4[0]; bf[2*p  ][1] = t4[2];
                bf[2*p+1][0] = t4[1]; bf[2*p+1][1] = t4[3];
            }
            #pragma unroll
            for (int n = 0; n < 8; n++) mma_f16(sacc[n], qf[kk], bf[n]);
        }

        // online softmax, log2 domain
        float t0 = -1e30f, t1 = -1e30f;
        #pragma unroll
        for (int n = 0; n < 8; n++) {
            t0 = fmaxf(t0, fmaxf(sacc[n][0], sacc[n][1]));
            t1 = fmaxf(t1, fmaxf(sacc[n][2], sacc[n][3]));
        }
        t0 = fmaxf(t0, __shfl_xor_sync(0xffffffffu, t0, 1));
        t0 = fmaxf(t0, __shfl_xor_sync(0xffffffffu, t0, 2));
        t1 = fmaxf(t1, __shfl_xor_sync(0xffffffffu, t1, 1));
        t1 = fmaxf(t1, __shfl_xor_sync(0xffffffffu, t1, 2));

        float mn0 = fmaxf(m0, t0), mn1 = fmaxf(m1, t1);
        float c0 = fexp2(m0 - mn0), c1 = fexp2(m1 - mn1);
        m0 = mn0; m1 = mn1;

        uint32_t ph0[8], ph1[8];
        #pragma unroll
        for (int n = 0; n < 8; n++) {
            ph0[n] = h2exp2(sacc[n][0] - m0, sacc[n][1] - m0);
            ph1[n] = h2exp2(sacc[n][2] - m1, sacc[n][3] - m1);
        }

        #pragma unroll
        for (int n = 0; n < 8; n++) {
            oacc[n][0] *= c0; oacc[n][1] *= c0;
            oacc[n][2] *= c1; oacc[n][3] *= c1;
        }
        lacc[0] *= c0; lacc[1] *= c0;
        lacc[2] *= c1; lacc[3] *= c1;

        #pragma unroll
        for (int ks = 0; ks < 4; ks++) {
            uint32_t af[4];
            af[0] = ph0[2*ks];   af[1] = ph1[2*ks];
            af[2] = ph0[2*ks+1]; af[3] = ph1[2*ks+1];
            mma_f16(lacc, af, bones);
            const uint32_t vrow = (uint32_t)((ks*16 + jr + l7) * 128);
            #pragma unroll
            for (int p = 0; p < 4; p++) {
                uint32_t t4[4];
                ldsm4t(t4, Vst + vrow + (uint32_t)((((p << 1) | jc) ^ l7) << 4));
                uint32_t bv0[2] = { t4[0], t4[1] };
                uint32_t bv1[2] = { t4[2], t4[3] };
                mma_f16(oacc[2*p  ], af, bv0);
                mma_f16(oacc[2*p+1], af, bv1);
            }
        }
        so = (so == 2) ? 0 : so + 1;
    }

    float i0 = 1.f / lacc[0], i1 = 1.f / lacc[2];
    __half* Op = Ob + (size_t)b * (Nseq * Dmod) + (size_t)h * DHd + (size_t)(qrow + g) * Dmod;
    #pragma unroll
    for (int n = 0; n < 8; n++) {
        *(__half2*)(Op + n*8 + tig*2)          = __floats2half2_rn(oacc[n][0]*i0, oacc[n][1]*i0);
        *(__half2*)(Op + 8*Dmod + n*8 + tig*2) = __floats2half2_rn(oacc[n][2]*i1, oacc[n][3]*i1);
    }
}

// ---------------- LayerNorm(1024) + exact GELU, fp16, 2-stream ----------------
__global__ __launch_bounds__(256) void ln_gelu_h(
    __half* __restrict__ Hm0, __half* __restrict__ Hm1,
    const float* __restrict__ gw, const float* __restrict__ bw)
{
    __shared__ float red1[8];
    __shared__ float red2[8];
    __shared__ float s_mu, s_inv;

    const int row = blockIdx.x;
    const int tid = threadIdx.x;
    __half* hp = (blockIdx.y ? Hm1 : Hm0) + (size_t)row * FFd;

    float v[4];
    float s = 0.f;
    #pragma unroll
    for (int i = 0; i < 4; i++) { v[i] = __half2float(hp[tid + i*256]); s += v[i]; }

    #pragma unroll
    for (int off = 16; off; off >>= 1) s += __shfl_xor_sync(0xffffffffu, s, off);
    if ((tid & 31) == 0) red1[tid >> 5] = s;
    __syncthreads();
    if (tid == 0) {
        float t = 0.f;
        #pragma unroll
        for (int w = 0; w < 8; w++) t += red1[w];
        s_mu = t * (1.f / FFd);
    }
    __syncthreads();
    const float mu = s_mu;

    float ss = 0.f;
    #pragma unroll
    for (int i = 0; i < 4; i++) { float d = v[i] - mu; ss += d*d; }
    #pragma unroll
    for (int off = 16; off; off >>= 1) ss += __shfl_xor_sync(0xffffffffu, ss, off);
    if ((tid & 31) == 0) red2[tid >> 5] = ss;
    __syncthreads();
    if (tid == 0) {
        float t = 0.f;
        #pragma unroll
        for (int w = 0; w < 8; w++) t += red2[w];
        s_inv = rsqrtf(t * (1.f / FFd) + 1e-5f);
    }
    __syncthreads();
    const float inv = s_inv;

    #pragma unroll
    for (int i = 0; i < 4; i++) {
        int c = tid + i*256;
        float x = (v[i] - mu) * inv * gw[c] + bw[c];
        hp[c] = __float2half_rn(0.5f * x * (1.f + erff(x * 0.70710678118654752f)));
    }
}

// ---------------- launcher ----------------
extern "C" void kernel_launch(void* const* d_in, const int* in_sizes, int n_in,
                              void* d_out, int out_size)
{
    const float* x0  = (const float*)d_in[0];
    const float* x1  = (const float*)d_in[1];
    const float* Wqk = (const float*)d_in[2];
    const float* bqk = (const float*)d_in[3];
    const float* Wv  = (const float*)d_in[4];
    const float* bv  = (const float*)d_in[5];
    const float* Wo  = (const float*)d_in[6];
    const float* bo  = (const float*)d_in[7];
    const float* Wf1 = (const float*)d_in[8];
    const float* bf1 = (const float*)d_in[9];
    const float* lng = (const float*)d_in[10];
    const float* lnb = (const float*)d_in[11];
    const float* Wf2 = (const float*)d_in[12];
    const float* bf2 = (const float*)d_in[13];
    float* out = (float*)d_out;

    __half *hx0, *hx1, *qkv0, *qkv1, *ha0, *ha1, *hm0, *hm1, *hmid0, *hmid1;
    __half *hwqk, *hwv, *hwo, *hwf1, *hwf2;
    cudaGetSymbolAddress((void**)&hx0,   g_hx0);
    cudaGetSymbolAddress((void**)&hx1,   g_hx1);
    cudaGetSymbolAddress((void**)&qkv0,  g_qkv0);
    cudaGetSymbolAddress((void**)&qkv1,  g_qkv1);
    cudaGetSymbolAddress((void**)&ha0,   g_ha0);
    cudaGetSymbolAddress((void**)&ha1,   g_ha1);
    cudaGetSymbolAddress((void**)&hm0,   g_hm0);
    cudaGetSymbolAddress((void**)&hm1,   g_hm1);
    cudaGetSymbolAddress((void**)&hmid0, g_hmid0);
    cudaGetSymbolAddress((void**)&hmid1, g_hmid1);
    cudaGetSymbolAddress((void**)&hwqk,  g_hwqk);
    cudaGetSymbolAddress((void**)&hwv,   g_hwv);
    cudaGetSymbolAddress((void**)&hwo,   g_hwo);
    cudaGetSymbolAddress((void**)&hwf1,  g_hwf1);
    cudaGetSymbolAddress((void**)&hwf2,  g_hwf2);

    cudaFuncSetAttribute(gemm_h<false,true>,  cudaFuncAttributeMaxDynamicSharedMemorySize, GSMEM);
    cudaFuncSetAttribute(gemm_h<false,false>, cudaFuncAttributeMaxDynamicSharedMemorySize, GSMEM);
    cudaFuncSetAttribute(gemm_h<true,true>,   cudaFuncAttributeMaxDynamicSharedMemorySize, GSMEM);
    cudaFuncSetAttribute(attn_h, cudaFuncAttributeMaxDynamicSharedMemorySize, ATTN_SMEM);

    const long totalConv = R_END / 4;
    f2h_all<<<(int)((totalConv + 255) / 256), 256>>>(
        x0, x1, Wqk, Wv, Wo, Wf1, Wf2,
        hx0, hx1, hwqk, hwv, hwo, hwf1, hwf2);

    const int BIG = 1 << 28;
    dim3 gproj(FFd/128, Mrows/128, 2);
    dim3 g512z(Dmod/128, Mrows/128, 2);
    dim3 g1024z(FFd/128, Mrows/128, 2);
    dim3 ga(Bsz*Hh, Nseq/128, 2);
    dim3 gln(Mrows, 2);

    // fused QK+V projection -> qkv [M][1024]
    gemm_h<false,true><<<gproj, 256, GSMEM>>>(
        hx0, hx1, nullptr, nullptr, hwqk, hwv, bqk, bv,
        nullptr, nullptr, nullptr, nullptr, qkv0, qkv1, FFd, Dmod, Dmod);

    // cross attention (both directions)
    attn_h<<<ga, 256, ATTN_SMEM>>>(qkv0, qkv1, ha0, ha1);

    // output projection -> hm
    gemm_h<false,true><<<g512z, 256, GSMEM>>>(
        ha0, ha1, nullptr, nullptr, hwo, hwo, bo, bo,
        nullptr, nullptr, nullptr, nullptr, hm0, hm1, Dmod, Dmod, BIG);

    // FFN1 (concat fused) -> hmid
    gemm_h<true,true><<<g1024z, 256, GSMEM>>>(
        hx0, hx1, hm0, hm1, hwf1, hwf1, bf1, bf1,
        nullptr, nullptr, nullptr, nullptr, hmid0, hmid1, FFd, FFd, BIG);

    // LayerNorm + GELU
    ln_gelu_h<<<gln, 256>>>(hmid0, hmid1, lng, lnb);

    // FFN2 + residual -> out (fp32)
    gemm_h<false,false><<<g512z, 256, GSMEM>>>(
        hmid0, hmid1, nullptr, nullptr, hwf2, hwf2, bf2, bf2,
        x0, x1, out, out + (size_t)Mrows*Dmod, nullptr, nullptr, Dmod, FFd, BIG);
}